// round 2
// baseline (speedup 1.0000x reference)
#include <cuda_runtime.h>
#include <cuda_bf16.h>
#include <cstdint>
#include <cstddef>

// ---------------------------------------------------------------------------
// Problem constants
//   B=2, T=2048, HID=2048, NH=16, NKV=8, HD=128, RANK=16, THETA=1e6
//   out = [ y (B*T*HID) | k_cache (B*T*NKV*HD) | v_cache (B*T*NKV*HD) ]
// ---------------------------------------------------------------------------
#define BB      2
#define TT      2048
#define HID     2048
#define NH      16
#define NKV     8
#define HD      128
#define RANK    16
#define BT      (BB*TT)              // 4096
#define QKV_N   (NH*HD + 2*NKV*HD)   // 4096
#define Y_ELEMS (BT*HID)             // 8388608
#define KV_ELEMS (BT*NKV*HD)         // 2097152
#define KOFF    Y_ELEMS
#define VOFF    (Y_ELEMS + KV_ELEMS)

#define LOG2_THETA 19.9315685693241741f   // log2(1e6)
#define SM_SCALE   0.0883883476483184405f // 1/sqrt(128)

// ---------------------------------------------------------------------------
// Device scratch (static globals: no allocation allowed)
// ---------------------------------------------------------------------------
__device__ float g_weff [HID * QKV_N];     // 2048 x 4096  (Wq|Wk|Wv + LoRA)
__device__ float g_woeff[HID * HID];       // 2048 x 2048  (Wo + LoRA)
__device__ float g_qkv  [BT * QKV_N];      // 4096 x 4096
__device__ float g_q    [BT * NH * HD];    // 4096 x 2048  (normed, roped, pre-scaled)
__device__ float g_k    [BT * NKV * HD];   // 4096 x 1024  (normed, roped)
__device__ float g_v    [BT * NKV * HD];   // 4096 x 1024
__device__ float g_attn [BT * NH * HD];    // 4096 x 2048

// ---------------------------------------------------------------------------
// W_eff for fused QKV:  g_weff[h][j] = W*[h][jj] + sum_r A*[h][r]*B*[r][jj]
// ---------------------------------------------------------------------------
__global__ void __launch_bounds__(256) build_weff_qkv(
    const float* __restrict__ Wq, const float* __restrict__ Aq, const float* __restrict__ Bq,
    const float* __restrict__ Wk, const float* __restrict__ Ak, const float* __restrict__ Bk,
    const float* __restrict__ Wv, const float* __restrict__ Av, const float* __restrict__ Bv)
{
    int idx = blockIdx.x * 256 + threadIdx.x;
    if (idx >= HID * QKV_N) return;
    int h = idx >> 12;          // / 4096
    int j = idx & 4095;
    const float* W; const float* A; const float* Bm; int jj, n;
    if (j < 2048)       { W = Wq; A = Aq; Bm = Bq; jj = j;        n = 2048; }
    else if (j < 3072)  { W = Wk; A = Ak; Bm = Bk; jj = j - 2048; n = 1024; }
    else                { W = Wv; A = Av; Bm = Bv; jj = j - 3072; n = 1024; }
    float acc = W[(size_t)h * n + jj];
    #pragma unroll
    for (int r = 0; r < RANK; r++)
        acc += A[h * RANK + r] * Bm[r * n + jj];
    g_weff[idx] = acc;
}

__global__ void __launch_bounds__(256) build_woeff(
    const float* __restrict__ Wo, const float* __restrict__ Ao, const float* __restrict__ Bo)
{
    int idx = blockIdx.x * 256 + threadIdx.x;
    if (idx >= HID * HID) return;
    int h = idx >> 11;
    int j = idx & 2047;
    float acc = Wo[(size_t)h * HID + j];
    #pragma unroll
    for (int r = 0; r < RANK; r++)
        acc += Ao[h * RANK + r] * Bo[r * HID + j];
    g_woeff[idx] = acc;
}

// ---------------------------------------------------------------------------
// Classic 128x128x8 fp32 SGEMM, row-major NN: C[M,N] = A[M,K] @ B[K,N]
// M,N multiples of 128; K multiple of 8.
// ---------------------------------------------------------------------------
__global__ void __launch_bounds__(256) sgemm_nn(
    const float* __restrict__ A, const float* __restrict__ B, float* __restrict__ C,
    int M, int N, int K)
{
    __shared__ float As[8][128];
    __shared__ float Bs[8][128];
    const int tid = threadIdx.x;
    const int tx = tid & 15;
    const int ty = tid >> 4;
    const int bx = blockIdx.x;
    const int by = blockIdx.y;

    const float* Ab = A + (size_t)by * 128 * K;
    const float* Bb = B + (size_t)bx * 128;

    const int arow = tid >> 1;
    const int acol = (tid & 1) * 4;
    const int brow = tid >> 5;
    const int bcol = (tid & 31) * 4;

    float acc[8][8];
    #pragma unroll
    for (int i = 0; i < 8; i++)
        #pragma unroll
        for (int j = 0; j < 8; j++) acc[i][j] = 0.0f;

    #pragma unroll 1
    for (int kt = 0; kt < K; kt += 8) {
        float4 av = *(const float4*)(Ab + (size_t)arow * K + kt + acol);
        float4 bv = *(const float4*)(Bb + (size_t)(kt + brow) * N + bcol);
        As[acol + 0][arow] = av.x;
        As[acol + 1][arow] = av.y;
        As[acol + 2][arow] = av.z;
        As[acol + 3][arow] = av.w;
        *(float4*)(&Bs[brow][bcol]) = bv;
        __syncthreads();
        #pragma unroll
        for (int k = 0; k < 8; k++) {
            float a[8], b[8];
            *(float4*)(a)     = *(const float4*)(&As[k][ty * 8]);
            *(float4*)(a + 4) = *(const float4*)(&As[k][ty * 8 + 4]);
            *(float4*)(b)     = *(const float4*)(&Bs[k][tx * 8]);
            *(float4*)(b + 4) = *(const float4*)(&Bs[k][tx * 8 + 4]);
            #pragma unroll
            for (int i = 0; i < 8; i++)
                #pragma unroll
                for (int j = 0; j < 8; j++)
                    acc[i][j] += a[i] * b[j];
        }
        __syncthreads();
    }
    float* Cb = C + (size_t)(by * 128 + ty * 8) * N + bx * 128 + tx * 8;
    #pragma unroll
    for (int i = 0; i < 8; i++) {
        *(float4*)(Cb + (size_t)i * N)     = make_float4(acc[i][0], acc[i][1], acc[i][2], acc[i][3]);
        *(float4*)(Cb + (size_t)i * N + 4) = make_float4(acc[i][4], acc[i][5], acc[i][6], acc[i][7]);
    }
}

// ---------------------------------------------------------------------------
// Epilogue: per-head RMSNorm (q,k) + RoPE (q,k), scatter q/k/v.
// One block per token row; 8 warps, each handles 4 of 32 head-segments.
// q is pre-multiplied by sm_scale.  k/v also copied to d_out cache region.
// ---------------------------------------------------------------------------
__global__ void __launch_bounds__(256) qkv_epilogue(
    const int* __restrict__ positions,
    const float* __restrict__ qn_w, const float* __restrict__ kn_w,
    float* __restrict__ dout, int writeKV)
{
    const int bt = blockIdx.x;
    const int w  = threadIdx.x >> 5;
    const int l  = threadIdx.x & 31;

    const float p = (float)positions[bt];
    const float inv0 = exp2f(-(float)l        * (LOG2_THETA / 64.0f));
    const float inv1 = exp2f(-(float)(l + 32) * (LOG2_THETA / 64.0f));
    float s0, c0, s1, c1;
    sincosf(p * inv0, &s0, &c0);
    sincosf(p * inv1, &s1, &c1);

    const float* row = g_qkv + (size_t)bt * QKV_N;

    for (int seg = w; seg < 32; seg += 8) {
        const float* src = row + seg * HD;
        float x0 = src[l], x1 = src[l + 32], x2 = src[l + 64], x3 = src[l + 96];
        if (seg < 24) {
            // RMSNorm over this head's 128 values
            float ss = x0 * x0 + x1 * x1 + x2 * x2 + x3 * x3;
            #pragma unroll
            for (int off = 16; off; off >>= 1)
                ss += __shfl_xor_sync(0xffffffffu, ss, off);
            float inv = rsqrtf(ss * (1.0f / 128.0f) + 1e-6f);
            const float* nw = (seg < 16) ? qn_w : kn_w;
            float y0 = nw[l]      * x0 * inv;
            float y1 = nw[l + 32] * x1 * inv;
            float y2 = nw[l + 64] * x2 * inv;   // b half (d = l+64)
            float y3 = nw[l + 96] * x3 * inv;   // b half (d = l+96)
            // RoPE: pairs (l, l+64) and (l+32, l+96)
            float r0 = y0 * c0 - y2 * s0;
            float r2 = y2 * c0 + y0 * s0;
            float r1 = y1 * c1 - y3 * s1;
            float r3 = y3 * c1 + y1 * s1;
            if (seg < 16) {
                float* dst = g_q + (size_t)bt * (NH * HD) + seg * HD;
                dst[l]      = r0 * SM_SCALE;
                dst[l + 32] = r1 * SM_SCALE;
                dst[l + 64] = r2 * SM_SCALE;
                dst[l + 96] = r3 * SM_SCALE;
            } else {
                int kh = seg - 16;
                size_t off = (size_t)bt * (NKV * HD) + kh * HD;
                float* dst = g_k + off;
                dst[l] = r0; dst[l + 32] = r1; dst[l + 64] = r2; dst[l + 96] = r3;
                if (writeKV) {
                    float* dk = dout + KOFF + off;
                    dk[l] = r0; dk[l + 32] = r1; dk[l + 64] = r2; dk[l + 96] = r3;
                }
            }
        } else {
            int vh = seg - 24;
            size_t off = (size_t)bt * (NKV * HD) + vh * HD;
            float* dst = g_v + off;
            dst[l] = x0; dst[l + 32] = x1; dst[l + 64] = x2; dst[l + 96] = x3;
            if (writeKV) {
                float* dv = dout + VOFF + off;
                dv[l] = x0; dv[l + 32] = x1; dv[l + 64] = x2; dv[l + 96] = x3;
            }
        }
    }
}

// ---------------------------------------------------------------------------
// fp32 flash attention, causal, GQA (2 q-heads per kv-head).
// Tile: 128 queries x 128 keys, 256 threads, 8x8 per-thread fragments.
// K is stored d-major in smem (conflict-free float4 operand loads);
// V row-major in the same buffer after S is materialized.
// ---------------------------------------------------------------------------
#define SSTR 132
#define FA_SMEM_FLOATS (128*128 + 128*128 + 128*SSTR + 3*128)

__global__ void __launch_bounds__(256) flash_kernel()
{
    extern __shared__ float sm[];
    float* Qs = sm;                    // [128][128]
    float* KV = Qs + 128 * 128;        // [128][128] (Kt: d-major, then V: j-major)
    float* Ss = KV + 128 * 128;        // [128][SSTR]
    float* rm = Ss + 128 * SSTR;       // running max  [128]
    float* rl = rm + 128;              // running sum  [128]
    float* ra = rl + 128;              // alpha        [128]

    const int tid = threadIdx.x;
    const int qb  = blockIdx.x;        // query tile
    const int h   = blockIdx.y;        // q head
    const int b   = blockIdx.z;        // batch
    const int kvh = h >> 1;
    const int tx  = tid & 15;
    const int ty  = tid >> 4;

    // load Q tile (pre-scaled by sm_scale in epilogue)
    const float* Qg = g_q + ((size_t)(b * TT + qb * 128)) * (NH * HD) + h * HD;
    #pragma unroll
    for (int it = 0; it < 16; it++) {
        int lin = it * 256 + tid;
        int r = lin >> 5;
        int d = (lin & 31) * 4;
        *(float4*)(Qs + r * 128 + d) = *(const float4*)(Qg + (size_t)r * (NH * HD) + d);
    }
    if (tid < 128) { rm[tid] = -1e30f; rl[tid] = 0.0f; }

    float o[8][8];
    #pragma unroll
    for (int i = 0; i < 8; i++)
        #pragma unroll
        for (int d = 0; d < 8; d++) o[i][d] = 0.0f;
    __syncthreads();

    for (int kb = 0; kb <= qb; kb++) {
        // ---- load K tile transposed: KV[d][j] ----
        const float* Kg = g_k + ((size_t)(b * TT + kb * 128)) * (NKV * HD) + kvh * HD;
        #pragma unroll
        for (int it = 0; it < 16; it++) {
            int lin = it * 256 + tid;
            int j  = lin & 127;
            int d0 = (lin >> 7) * 4;
            float4 kv4 = *(const float4*)(Kg + (size_t)j * (NKV * HD) + d0);
            KV[(d0 + 0) * 128 + j] = kv4.x;
            KV[(d0 + 1) * 128 + j] = kv4.y;
            KV[(d0 + 2) * 128 + j] = kv4.z;
            KV[(d0 + 3) * 128 + j] = kv4.w;
        }
        __syncthreads();

        // ---- S = Q @ K^T (already scaled via Q) ----
        float s[8][8];
        #pragma unroll
        for (int i = 0; i < 8; i++)
            #pragma unroll
            for (int j = 0; j < 8; j++) s[i][j] = 0.0f;
        #pragma unroll 1
        for (int d = 0; d < 128; d++) {
            float kf[8], qf[8];
            *(float4*)(kf)     = *(const float4*)(KV + d * 128 + tx * 8);
            *(float4*)(kf + 4) = *(const float4*)(KV + d * 128 + tx * 8 + 4);
            #pragma unroll
            for (int i = 0; i < 8; i++) qf[i] = Qs[(ty * 8 + i) * 128 + d];
            #pragma unroll
            for (int i = 0; i < 8; i++)
                #pragma unroll
                for (int j = 0; j < 8; j++)
                    s[i][j] += qf[i] * kf[j];
        }

        // ---- write S with causal mask ----
        const bool diag = (kb == qb);
        #pragma unroll
        for (int i = 0; i < 8; i++) {
            int qi = ty * 8 + i;
            #pragma unroll
            for (int j = 0; j < 8; j++) {
                int kj = tx * 8 + j;
                float v = s[i][j];
                if (diag && kj > qi) v = -1e30f;
                Ss[qi * SSTR + kj] = v;
            }
        }
        __syncthreads();

        // ---- load V tile (row-major) into KV; overlaps with softmax row pass ----
        const float* Vg = g_v + ((size_t)(b * TT + kb * 128)) * (NKV * HD) + kvh * HD;
        #pragma unroll
        for (int it = 0; it < 16; it++) {
            int lin = it * 256 + tid;
            int j  = lin >> 5;
            int d0 = (lin & 31) * 4;
            *(float4*)(KV + j * 128 + d0) = *(const float4*)(Vg + (size_t)j * (NKV * HD) + d0);
        }

        // ---- online softmax row pass: 2 threads per row ----
        {
            int r    = tid >> 1;
            int half = tid & 1;
            float* Srow = Ss + r * SSTR + half * 64;
            float mloc = -1e30f;
            #pragma unroll 8
            for (int c = 0; c < 64; c++) mloc = fmaxf(mloc, Srow[c]);
            mloc = fmaxf(mloc, __shfl_xor_sync(0xffffffffu, mloc, 1));
            float mold = rm[r];
            float mnew = fmaxf(mold, mloc);
            float ssum = 0.0f;
            #pragma unroll 8
            for (int c = 0; c < 64; c++) {
                float pv = __expf(Srow[c] - mnew);
                Srow[c] = pv;
                ssum += pv;
            }
            ssum += __shfl_xor_sync(0xffffffffu, ssum, 1);
            if (half == 0) {
                float alpha = __expf(mold - mnew);
                ra[r] = alpha;
                rm[r] = mnew;
                rl[r] = rl[r] * alpha + ssum;
            }
        }
        __syncthreads();

        // ---- O = O*alpha + P @ V ----
        float al[8];
        #pragma unroll
        for (int i = 0; i < 8; i++) al[i] = ra[ty * 8 + i];
        #pragma unroll
        for (int i = 0; i < 8; i++)
            #pragma unroll
            for (int d = 0; d < 8; d++) o[i][d] *= al[i];

        #pragma unroll 1
        for (int j = 0; j < 128; j++) {
            float vf[8];
            *(float4*)(vf)     = *(const float4*)(KV + j * 128 + tx * 8);
            *(float4*)(vf + 4) = *(const float4*)(KV + j * 128 + tx * 8 + 4);
            #pragma unroll
            for (int i = 0; i < 8; i++) {
                float pv = Ss[(ty * 8 + i) * SSTR + j];
                #pragma unroll
                for (int d = 0; d < 8; d++)
                    o[i][d] += pv * vf[d];
            }
        }
        __syncthreads();   // protect Ss/KV before next tile
    }

    // ---- normalize and store ----
    float linv[8];
    #pragma unroll
    for (int i = 0; i < 8; i++) linv[i] = 1.0f / rl[ty * 8 + i];
    float* Og = g_attn + ((size_t)(b * TT + qb * 128 + ty * 8)) * (NH * HD) + h * HD + tx * 8;
    #pragma unroll
    for (int i = 0; i < 8; i++) {
        *(float4*)(Og + (size_t)i * (NH * HD)) =
            make_float4(o[i][0] * linv[i], o[i][1] * linv[i], o[i][2] * linv[i], o[i][3] * linv[i]);
        *(float4*)(Og + (size_t)i * (NH * HD) + 4) =
            make_float4(o[i][4] * linv[i], o[i][5] * linv[i], o[i][6] * linv[i], o[i][7] * linv[i]);
    }
}

// ---------------------------------------------------------------------------
// Host launcher
// ---------------------------------------------------------------------------
extern "C" void kernel_launch(void* const* d_in, const int* in_sizes, int n_in,
                              void* d_out, int out_size)
{
    const float* x  = (const float*)d_in[0];
    // d_in[1] = attention_mask (unused: all-ones, causal handled in kernel)
    const int*   positions = (const int*)d_in[2];
    const float* Wq = (const float*)d_in[3];
    const float* Aq = (const float*)d_in[4];
    const float* Bq = (const float*)d_in[5];
    const float* Wk = (const float*)d_in[6];
    const float* Ak = (const float*)d_in[7];
    const float* Bk = (const float*)d_in[8];
    const float* Wv = (const float*)d_in[9];
    const float* Av = (const float*)d_in[10];
    const float* Bv = (const float*)d_in[11];
    const float* Wo = (const float*)d_in[12];
    const float* Ao = (const float*)d_in[13];
    const float* Bo = (const float*)d_in[14];
    const float* qn = (const float*)d_in[15];
    const float* kn = (const float*)d_in[16];
    float* out = (float*)d_out;

    float *p_weff, *p_woeff, *p_qkv, *p_attn;
    cudaGetSymbolAddress((void**)&p_weff,  g_weff);
    cudaGetSymbolAddress((void**)&p_woeff, g_woeff);
    cudaGetSymbolAddress((void**)&p_qkv,   g_qkv);
    cudaGetSymbolAddress((void**)&p_attn,  g_attn);

    // 1) fold LoRA into effective weights
    build_weff_qkv<<<(HID * QKV_N + 255) / 256, 256>>>(Wq, Aq, Bq, Wk, Ak, Bk, Wv, Av, Bv);
    build_woeff<<<(HID * HID + 255) / 256, 256>>>(Wo, Ao, Bo);

    // 2) fused QKV projection: [4096,2048] @ [2048,4096]
    sgemm_nn<<<dim3(QKV_N / 128, BT / 128), 256>>>(x, p_weff, p_qkv, BT, QKV_N, HID);

    // 3) RMSNorm + RoPE + scatter (also writes k/v caches to d_out)
    int writeKV = (out_size >= VOFF + KV_ELEMS) ? 1 : 0;
    qkv_epilogue<<<BT, 256>>>(positions, qn, kn, out, writeKV);

    // 4) causal flash attention
    const int fa_smem = FA_SMEM_FLOATS * (int)sizeof(float);
    cudaFuncSetAttribute(flash_kernel, cudaFuncAttributeMaxDynamicSharedMemorySize, fa_smem);
    flash_kernel<<<dim3(TT / 128, NH, BB), 256, fa_smem>>>();

    // 5) output projection: [4096,2048] @ [2048,2048] -> y
    sgemm_nn<<<dim3(HID / 128, BT / 128), 256>>>(p_attn, p_woeff, out, BT, HID, HID);
}

// round 4
// speedup vs baseline: 1.6153x; 1.6153x over previous
#include <cuda_runtime.h>
#include <cuda_bf16.h>
#include <cstdint>
#include <cstddef>

// ---------------------------------------------------------------------------
// Problem constants
// ---------------------------------------------------------------------------
#define BB      2
#define TT      2048
#define HID     2048
#define NH      16
#define NKV     8
#define HD      128
#define RANK    16
#define BT      (BB*TT)              // 4096
#define QKV_N   (NH*HD + 2*NKV*HD)   // 4096
#define Y_ELEMS (BT*HID)             // 8388608
#define KV_ELEMS (BT*NKV*HD)         // 2097152
#define KOFF    Y_ELEMS
#define VOFF    (Y_ELEMS + KV_ELEMS)

#define LOG2_THETA 19.9315685693241741f
#define SM_SCALE   0.0883883476483184405f

// ---------------------------------------------------------------------------
// Device scratch
// ---------------------------------------------------------------------------
__device__ float g_weff [HID * QKV_N];     // tf32-rounded
__device__ float g_woeff[HID * HID];       // tf32-rounded
__device__ float g_xt   [BT * HID];        // tf32-rounded copy of x
__device__ float g_qkv  [BT * QKV_N];
__device__ float g_q    [BT * NH * HD];
__device__ float g_k    [BT * NKV * HD];
__device__ float g_v    [BT * NKV * HD];
__device__ float g_attn [BT * NH * HD];    // tf32-rounded (flash epilogue)

// ---------------------------------------------------------------------------
// Helpers
// ---------------------------------------------------------------------------
__device__ __forceinline__ float f2tf32(float x) {
    uint32_t u;
    asm("cvt.rna.tf32.f32 %0, %1;" : "=r"(u) : "f"(x));
    return __uint_as_float(u);
}

__device__ __forceinline__ void cp16(uint32_t dst, const void* src) {
    asm volatile("cp.async.cg.shared.global [%0], [%1], 16;" :: "r"(dst), "l"(src));
}

__device__ __forceinline__ void mma_tf32(float* d, const uint32_t* a, const uint32_t* b) {
    asm volatile(
        "mma.sync.aligned.m16n8k8.row.col.f32.tf32.tf32.f32 "
        "{%0,%1,%2,%3}, {%4,%5,%6,%7}, {%8,%9}, {%0,%1,%2,%3};"
        : "+f"(d[0]), "+f"(d[1]), "+f"(d[2]), "+f"(d[3])
        : "r"(a[0]), "r"(a[1]), "r"(a[2]), "r"(a[3]),
          "r"(b[0]), "r"(b[1]));
}

// ---------------------------------------------------------------------------
// LoRA fold (outputs tf32-rounded)
// ---------------------------------------------------------------------------
__global__ void __launch_bounds__(256) build_weff_qkv(
    const float* __restrict__ Wq, const float* __restrict__ Aq, const float* __restrict__ Bq,
    const float* __restrict__ Wk, const float* __restrict__ Ak, const float* __restrict__ Bk,
    const float* __restrict__ Wv, const float* __restrict__ Av, const float* __restrict__ Bv)
{
    int idx = blockIdx.x * 256 + threadIdx.x;
    if (idx >= HID * QKV_N) return;
    int h = idx >> 12;
    int j = idx & 4095;
    const float* W; const float* A; const float* Bm; int jj, n;
    if (j < 2048)       { W = Wq; A = Aq; Bm = Bq; jj = j;        n = 2048; }
    else if (j < 3072)  { W = Wk; A = Ak; Bm = Bk; jj = j - 2048; n = 1024; }
    else                { W = Wv; A = Av; Bm = Bv; jj = j - 3072; n = 1024; }
    float acc = W[(size_t)h * n + jj];
    #pragma unroll
    for (int r = 0; r < RANK; r++)
        acc += A[h * RANK + r] * Bm[r * n + jj];
    g_weff[idx] = f2tf32(acc);
}

__global__ void __launch_bounds__(256) build_woeff(
    const float* __restrict__ Wo, const float* __restrict__ Ao, const float* __restrict__ Bo)
{
    int idx = blockIdx.x * 256 + threadIdx.x;
    if (idx >= HID * HID) return;
    int h = idx >> 11;
    int j = idx & 2047;
    float acc = Wo[(size_t)h * HID + j];
    #pragma unroll
    for (int r = 0; r < RANK; r++)
        acc += Ao[h * RANK + r] * Bo[r * HID + j];
    g_woeff[idx] = f2tf32(acc);
}

// ---------------------------------------------------------------------------
// Round x to tf32 values
// ---------------------------------------------------------------------------
__global__ void __launch_bounds__(256) cvt_x_tf32(const float* __restrict__ x)
{
    int idx = blockIdx.x * 256 + threadIdx.x;   // float4 index
    const float4 v = ((const float4*)x)[idx];
    float4 o;
    o.x = f2tf32(v.x); o.y = f2tf32(v.y); o.z = f2tf32(v.z); o.w = f2tf32(v.w);
    ((float4*)g_xt)[idx] = o;
}

// ---------------------------------------------------------------------------
// tf32 tensor-core GEMM, NN row-major: C[M,N] = A[M,K] @ B[K,N]
// Block 128x128x32, 256 threads (8 warps of 64x32), cp.async double buffer.
// Operand values must already be tf32-representable.
// ---------------------------------------------------------------------------
#define BM  128
#define BN  128
#define BKK 32
#define AST 36      // A smem row stride  (bank = 4g + c : conflict-free)
#define BST 136     // B smem row stride  (bank = 8c + g : conflict-free)
#define SMEM_A_FLOATS (2*BM*AST)            // 9216
#define SMEM_B_FLOATS (2*BKK*BST)           // 8704
#define GEMM_SMEM_BYTES ((SMEM_A_FLOATS + SMEM_B_FLOATS) * 4)   // 71680

__global__ void __launch_bounds__(256, 2) sgemm_tf32(
    const float* __restrict__ A, const float* __restrict__ B, float* __restrict__ C,
    int M, int N, int K)
{
    extern __shared__ float smem[];
    float* sA = smem;                       // [2][BM][AST]
    float* sB = smem + SMEM_A_FLOATS;       // [2][BKK][BST]
    const uint32_t smem_base = (uint32_t)__cvta_generic_to_shared(smem);

    const int tid  = threadIdx.x;
    const int lane = tid & 31;
    const int wid  = tid >> 5;
    const int wr   = wid >> 2;          // 0..1
    const int wc   = wid & 3;           // 0..3
    const int g    = lane >> 2;         // 0..7
    const int c    = lane & 3;          // 0..3
    const int bm   = blockIdx.y * BM;
    const int bn   = blockIdx.x * BN;

    // loader mapping
    const int am  = tid >> 1;            // 0..127
    const int ak  = (tid & 1) * 16;      // 0 or 16
    const int bk  = tid >> 3;            // 0..31
    const int bnn = (tid & 7) * 16;      // 0..112

    const float* Aptr = A + (size_t)(bm + am) * K + ak;
    const float* Bptr = B + (size_t)bk * N + bn + bnn;
    const uint32_t dA0 = smem_base + (uint32_t)((am * AST + ak) * 4);
    const uint32_t dB0 = smem_base + (uint32_t)((SMEM_A_FLOATS + bk * BST + bnn) * 4);

    float acc[4][4][4];
    #pragma unroll
    for (int mt = 0; mt < 4; mt++)
        #pragma unroll
        for (int nt = 0; nt < 4; nt++)
            #pragma unroll
            for (int i = 0; i < 4; i++) acc[mt][nt][i] = 0.0f;

    const int nkt = K / BKK;

    // prefetch tile 0 -> buf 0
    {
        const float* pa = Aptr;
        const float* pb = Bptr;
        #pragma unroll
        for (int i = 0; i < 4; i++) cp16(dA0 + i * 16, pa + i * 4);
        #pragma unroll
        for (int i = 0; i < 4; i++) cp16(dB0 + i * 16, pb + i * 4);
        asm volatile("cp.async.commit_group;");
    }

    for (int kt = 0; kt < nkt; kt++) {
        const int buf = kt & 1;
        if (kt + 1 < nkt) {
            const int nb = buf ^ 1;
            const float* pa = Aptr + (kt + 1) * BKK;
            const float* pb = Bptr + (size_t)(kt + 1) * BKK * N;
            const uint32_t da = dA0 + (uint32_t)(nb * BM * AST * 4);
            const uint32_t db = dB0 + (uint32_t)(nb * BKK * BST * 4);
            #pragma unroll
            for (int i = 0; i < 4; i++) cp16(da + i * 16, pa + i * 4);
            #pragma unroll
            for (int i = 0; i < 4; i++) cp16(db + i * 16, pb + i * 4);
            asm volatile("cp.async.commit_group;");
            asm volatile("cp.async.wait_group 1;");
        } else {
            asm volatile("cp.async.wait_group 0;");
        }
        __syncthreads();

        const uint32_t* Au = (const uint32_t*)(sA + buf * BM * AST);
        const uint32_t* Bu = (const uint32_t*)(sB + buf * BKK * BST);

        #pragma unroll
        for (int ks = 0; ks < 4; ks++) {
            const int kk = ks * 8;
            uint32_t af[4][4], bf[4][2];
            #pragma unroll
            for (int mt = 0; mt < 4; mt++) {
                const int r0 = wr * 64 + mt * 16 + g;
                af[mt][0] = Au[r0 * AST + kk + c];
                af[mt][1] = Au[(r0 + 8) * AST + kk + c];
                af[mt][2] = Au[r0 * AST + kk + c + 4];
                af[mt][3] = Au[(r0 + 8) * AST + kk + c + 4];
            }
            #pragma unroll
            for (int nt = 0; nt < 4; nt++) {
                const int n0 = wc * 32 + nt * 8 + g;
                bf[nt][0] = Bu[(kk + c) * BST + n0];
                bf[nt][1] = Bu[(kk + c + 4) * BST + n0];
            }
            #pragma unroll
            for (int mt = 0; mt < 4; mt++)
                #pragma unroll
                for (int nt = 0; nt < 4; nt++)
                    mma_tf32(acc[mt][nt], af[mt], bf[nt]);
        }
        __syncthreads();
    }

    // epilogue
    #pragma unroll
    for (int mt = 0; mt < 4; mt++) {
        const int r0 = bm + wr * 64 + mt * 16 + g;
        #pragma unroll
        for (int nt = 0; nt < 4; nt++) {
            const int col = bn + wc * 32 + nt * 8 + 2 * c;
            *(float2*)&C[(size_t)r0 * N + col]       = make_float2(acc[mt][nt][0], acc[mt][nt][1]);
            *(float2*)&C[(size_t)(r0 + 8) * N + col] = make_float2(acc[mt][nt][2], acc[mt][nt][3]);
        }
    }
}

// ---------------------------------------------------------------------------
// Epilogue: per-head RMSNorm + RoPE, scatter q/k/v (unchanged)
// ---------------------------------------------------------------------------
__global__ void __launch_bounds__(256) qkv_epilogue(
    const int* __restrict__ positions,
    const float* __restrict__ qn_w, const float* __restrict__ kn_w,
    float* __restrict__ dout, int writeKV)
{
    const int bt = blockIdx.x;
    const int w  = threadIdx.x >> 5;
    const int l  = threadIdx.x & 31;

    const float p = (float)positions[bt];
    const float inv0 = exp2f(-(float)l        * (LOG2_THETA / 64.0f));
    const float inv1 = exp2f(-(float)(l + 32) * (LOG2_THETA / 64.0f));
    float s0, c0, s1, c1;
    sincosf(p * inv0, &s0, &c0);
    sincosf(p * inv1, &s1, &c1);

    const float* row = g_qkv + (size_t)bt * QKV_N;

    for (int seg = w; seg < 32; seg += 8) {
        const float* src = row + seg * HD;
        float x0 = src[l], x1 = src[l + 32], x2 = src[l + 64], x3 = src[l + 96];
        if (seg < 24) {
            float ss = x0 * x0 + x1 * x1 + x2 * x2 + x3 * x3;
            #pragma unroll
            for (int off = 16; off; off >>= 1)
                ss += __shfl_xor_sync(0xffffffffu, ss, off);
            float inv = rsqrtf(ss * (1.0f / 128.0f) + 1e-6f);
            const float* nw = (seg < 16) ? qn_w : kn_w;
            float y0 = nw[l]      * x0 * inv;
            float y1 = nw[l + 32] * x1 * inv;
            float y2 = nw[l + 64] * x2 * inv;
            float y3 = nw[l + 96] * x3 * inv;
            float r0 = y0 * c0 - y2 * s0;
            float r2 = y2 * c0 + y0 * s0;
            float r1 = y1 * c1 - y3 * s1;
            float r3 = y3 * c1 + y1 * s1;
            if (seg < 16) {
                float* dst = g_q + (size_t)bt * (NH * HD) + seg * HD;
                dst[l]      = r0 * SM_SCALE;
                dst[l + 32] = r1 * SM_SCALE;
                dst[l + 64] = r2 * SM_SCALE;
                dst[l + 96] = r3 * SM_SCALE;
            } else {
                int kh = seg - 16;
                size_t off = (size_t)bt * (NKV * HD) + kh * HD;
                float* dst = g_k + off;
                dst[l] = r0; dst[l + 32] = r1; dst[l + 64] = r2; dst[l + 96] = r3;
                if (writeKV) {
                    float* dk = dout + KOFF + off;
                    dk[l] = r0; dk[l + 32] = r1; dk[l + 64] = r2; dk[l + 96] = r3;
                }
            }
        } else {
            int vh = seg - 24;
            size_t off = (size_t)bt * (NKV * HD) + vh * HD;
            float* dst = g_v + off;
            dst[l] = x0; dst[l + 32] = x1; dst[l + 64] = x2; dst[l + 96] = x3;
            if (writeKV) {
                float* dv = dout + VOFF + off;
                dv[l] = x0; dv[l + 32] = x1; dv[l + 64] = x2; dv[l + 96] = x3;
            }
        }
    }
}

// ---------------------------------------------------------------------------
// fp32 flash attention (unchanged except tf32-rounded output for O-proj)
// ---------------------------------------------------------------------------
#define SSTR 132
#define FA_SMEM_FLOATS (128*128 + 128*128 + 128*SSTR + 3*128)

__global__ void __launch_bounds__(256) flash_kernel()
{
    extern __shared__ float sm[];
    float* Qs = sm;
    float* KV = Qs + 128 * 128;
    float* Ss = KV + 128 * 128;
    float* rm = Ss + 128 * SSTR;
    float* rl = rm + 128;
    float* ra = rl + 128;

    const int tid = threadIdx.x;
    const int qb  = blockIdx.x;
    const int h   = blockIdx.y;
    const int b   = blockIdx.z;
    const int kvh = h >> 1;
    const int tx  = tid & 15;
    const int ty  = tid >> 4;

    const float* Qg = g_q + ((size_t)(b * TT + qb * 128)) * (NH * HD) + h * HD;
    #pragma unroll
    for (int it = 0; it < 16; it++) {
        int lin = it * 256 + tid;
        int r = lin >> 5;
        int d = (lin & 31) * 4;
        *(float4*)(Qs + r * 128 + d) = *(const float4*)(Qg + (size_t)r * (NH * HD) + d);
    }
    if (tid < 128) { rm[tid] = -1e30f; rl[tid] = 0.0f; }

    float o[8][8];
    #pragma unroll
    for (int i = 0; i < 8; i++)
        #pragma unroll
        for (int d = 0; d < 8; d++) o[i][d] = 0.0f;
    __syncthreads();

    for (int kb = 0; kb <= qb; kb++) {
        const float* Kg = g_k + ((size_t)(b * TT + kb * 128)) * (NKV * HD) + kvh * HD;
        #pragma unroll
        for (int it = 0; it < 16; it++) {
            int lin = it * 256 + tid;
            int j  = lin & 127;
            int d0 = (lin >> 7) * 4;
            float4 kv4 = *(const float4*)(Kg + (size_t)j * (NKV * HD) + d0);
            KV[(d0 + 0) * 128 + j] = kv4.x;
            KV[(d0 + 1) * 128 + j] = kv4.y;
            KV[(d0 + 2) * 128 + j] = kv4.z;
            KV[(d0 + 3) * 128 + j] = kv4.w;
        }
        __syncthreads();

        float s[8][8];
        #pragma unroll
        for (int i = 0; i < 8; i++)
            #pragma unroll
            for (int j = 0; j < 8; j++) s[i][j] = 0.0f;
        #pragma unroll 1
        for (int d = 0; d < 128; d++) {
            float kf[8], qf[8];
            *(float4*)(kf)     = *(const float4*)(KV + d * 128 + tx * 8);
            *(float4*)(kf + 4) = *(const float4*)(KV + d * 128 + tx * 8 + 4);
            #pragma unroll
            for (int i = 0; i < 8; i++) qf[i] = Qs[(ty * 8 + i) * 128 + d];
            #pragma unroll
            for (int i = 0; i < 8; i++)
                #pragma unroll
                for (int j = 0; j < 8; j++)
                    s[i][j] += qf[i] * kf[j];
        }

        const bool diag = (kb == qb);
        #pragma unroll
        for (int i = 0; i < 8; i++) {
            int qi = ty * 8 + i;
            #pragma unroll
            for (int j = 0; j < 8; j++) {
                int kj = tx * 8 + j;
                float v = s[i][j];
                if (diag && kj > qi) v = -1e30f;
                Ss[qi * SSTR + kj] = v;
            }
        }
        __syncthreads();

        const float* Vg = g_v + ((size_t)(b * TT + kb * 128)) * (NKV * HD) + kvh * HD;
        #pragma unroll
        for (int it = 0; it < 16; it++) {
            int lin = it * 256 + tid;
            int j  = lin >> 5;
            int d0 = (lin & 31) * 4;
            *(float4*)(KV + j * 128 + d0) = *(const float4*)(Vg + (size_t)j * (NKV * HD) + d0);
        }

        {
            int r    = tid >> 1;
            int half = tid & 1;
            float* Srow = Ss + r * SSTR + half * 64;
            float mloc = -1e30f;
            #pragma unroll 8
            for (int cc = 0; cc < 64; cc++) mloc = fmaxf(mloc, Srow[cc]);
            mloc = fmaxf(mloc, __shfl_xor_sync(0xffffffffu, mloc, 1));
            float mold = rm[r];
            float mnew = fmaxf(mold, mloc);
            float ssum = 0.0f;
            #pragma unroll 8
            for (int cc = 0; cc < 64; cc++) {
                float pv = __expf(Srow[cc] - mnew);
                Srow[cc] = pv;
                ssum += pv;
            }
            ssum += __shfl_xor_sync(0xffffffffu, ssum, 1);
            if (half == 0) {
                float alpha = __expf(mold - mnew);
                ra[r] = alpha;
                rm[r] = mnew;
                rl[r] = rl[r] * alpha + ssum;
            }
        }
        __syncthreads();

        float al[8];
        #pragma unroll
        for (int i = 0; i < 8; i++) al[i] = ra[ty * 8 + i];
        #pragma unroll
        for (int i = 0; i < 8; i++)
            #pragma unroll
            for (int d = 0; d < 8; d++) o[i][d] *= al[i];

        #pragma unroll 1
        for (int j = 0; j < 128; j++) {
            float vf[8];
            *(float4*)(vf)     = *(const float4*)(KV + j * 128 + tx * 8);
            *(float4*)(vf + 4) = *(const float4*)(KV + j * 128 + tx * 8 + 4);
            #pragma unroll
            for (int i = 0; i < 8; i++) {
                float pv = Ss[(ty * 8 + i) * SSTR + j];
                #pragma unroll
                for (int d = 0; d < 8; d++)
                    o[i][d] += pv * vf[d];
            }
        }
        __syncthreads();
    }

    float linv[8];
    #pragma unroll
    for (int i = 0; i < 8; i++) linv[i] = 1.0f / rl[ty * 8 + i];
    float* Og = g_attn + ((size_t)(b * TT + qb * 128 + ty * 8)) * (NH * HD) + h * HD + tx * 8;
    #pragma unroll
    for (int i = 0; i < 8; i++) {
        *(float4*)(Og + (size_t)i * (NH * HD)) =
            make_float4(f2tf32(o[i][0] * linv[i]), f2tf32(o[i][1] * linv[i]),
                        f2tf32(o[i][2] * linv[i]), f2tf32(o[i][3] * linv[i]));
        *(float4*)(Og + (size_t)i * (NH * HD) + 4) =
            make_float4(f2tf32(o[i][4] * linv[i]), f2tf32(o[i][5] * linv[i]),
                        f2tf32(o[i][6] * linv[i]), f2tf32(o[i][7] * linv[i]));
    }
}

// ---------------------------------------------------------------------------
// Host launcher
// ---------------------------------------------------------------------------
extern "C" void kernel_launch(void* const* d_in, const int* in_sizes, int n_in,
                              void* d_out, int out_size)
{
    const float* x  = (const float*)d_in[0];
    const int*   positions = (const int*)d_in[2];
    const float* Wq = (const float*)d_in[3];
    const float* Aq = (const float*)d_in[4];
    const float* Bq = (const float*)d_in[5];
    const float* Wk = (const float*)d_in[6];
    const float* Ak = (const float*)d_in[7];
    const float* Bk = (const float*)d_in[8];
    const float* Wv = (const float*)d_in[9];
    const float* Av = (const float*)d_in[10];
    const float* Bv = (const float*)d_in[11];
    const float* Wo = (const float*)d_in[12];
    const float* Ao = (const float*)d_in[13];
    const float* Bo = (const float*)d_in[14];
    const float* qn = (const float*)d_in[15];
    const float* kn = (const float*)d_in[16];
    float* out = (float*)d_out;

    float *p_weff, *p_woeff, *p_xt, *p_qkv, *p_attn;
    cudaGetSymbolAddress((void**)&p_weff,  g_weff);
    cudaGetSymbolAddress((void**)&p_woeff, g_woeff);
    cudaGetSymbolAddress((void**)&p_xt,    g_xt);
    cudaGetSymbolAddress((void**)&p_qkv,   g_qkv);
    cudaGetSymbolAddress((void**)&p_attn,  g_attn);

    // 1) fold LoRA into tf32-rounded effective weights; round x
    build_weff_qkv<<<(HID * QKV_N + 255) / 256, 256>>>(Wq, Aq, Bq, Wk, Ak, Bk, Wv, Av, Bv);
    build_woeff<<<(HID * HID + 255) / 256, 256>>>(Wo, Ao, Bo);
    cvt_x_tf32<<<(BT * HID / 4 + 255) / 256, 256>>>(x);

    // 2) fused QKV projection (tf32 tensor cores)
    cudaFuncSetAttribute(sgemm_tf32, cudaFuncAttributeMaxDynamicSharedMemorySize, GEMM_SMEM_BYTES);
    sgemm_tf32<<<dim3(QKV_N / BN, BT / BM), 256, GEMM_SMEM_BYTES>>>(p_xt, p_weff, p_qkv, BT, QKV_N, HID);

    // 3) RMSNorm + RoPE + scatter
    int writeKV = (out_size >= VOFF + KV_ELEMS) ? 1 : 0;
    qkv_epilogue<<<BT, 256>>>(positions, qn, kn, out, writeKV);

    // 4) causal flash attention (fp32)
    const int fa_smem = FA_SMEM_FLOATS * (int)sizeof(float);
    cudaFuncSetAttribute(flash_kernel, cudaFuncAttributeMaxDynamicSharedMemorySize, fa_smem);
    flash_kernel<<<dim3(TT / 128, NH, BB), 256, fa_smem>>>();

    // 5) output projection (tf32 tensor cores)
    sgemm_tf32<<<dim3(HID / BN, BT / BM), 256, GEMM_SMEM_BYTES>>>(p_attn, p_woeff, out, BT, HID, HID);
}

// round 6
// speedup vs baseline: 3.5023x; 2.1682x over previous
#include <cuda_runtime.h>
#include <cuda_fp16.h>
#include <cuda_bf16.h>
#include <cstdint>
#include <cstddef>

// ---------------------------------------------------------------------------
// Problem constants
// ---------------------------------------------------------------------------
#define BB      2
#define TT      2048
#define HID     2048
#define NH      16
#define NKV     8
#define HD      128
#define RANK    16
#define BT      (BB*TT)              // 4096
#define QKV_N   (NH*HD + 2*NKV*HD)   // 4096
#define Y_ELEMS (BT*HID)             // 8388608
#define KV_ELEMS (BT*NKV*HD)         // 2097152
#define KOFF    Y_ELEMS
#define VOFF    (Y_ELEMS + KV_ELEMS)

#define LOG2_THETA 19.9315685693241741f
#define SM_SCALE   0.0883883476483184405f

// ---------------------------------------------------------------------------
// Device scratch
// ---------------------------------------------------------------------------
__device__ float  g_weff [HID * QKV_N];     // tf32-rounded
__device__ float  g_woeff[HID * HID];       // tf32-rounded
__device__ float  g_xt   [BT * HID];        // tf32-rounded copy of x
__device__ float  g_qkv  [BT * QKV_N];
__device__ __half g_qh   [BT * NH * HD];    // fp16 q (normed, roped, pre-scaled)
__device__ __half g_kh   [BT * NKV * HD];   // fp16 k (normed, roped), row-major
__device__ __half g_vt   [BB * NKV * HD * TT]; // fp16 v, TRANSPOSED: [(b,kvh)][d][t]
__device__ float  g_attn [BT * NH * HD];    // tf32-rounded (flash epilogue)

// ---------------------------------------------------------------------------
// Helpers
// ---------------------------------------------------------------------------
__device__ __forceinline__ float f2tf32(float x) {
    uint32_t u;
    asm("cvt.rna.tf32.f32 %0, %1;" : "=r"(u) : "f"(x));
    return __uint_as_float(u);
}

__device__ __forceinline__ void cp16(uint32_t dst, const void* src) {
    asm volatile("cp.async.cg.shared.global [%0], [%1], 16;" :: "r"(dst), "l"(src));
}

__device__ __forceinline__ void mma_tf32(float* d, const uint32_t* a, const uint32_t* b) {
    asm volatile(
        "mma.sync.aligned.m16n8k8.row.col.f32.tf32.tf32.f32 "
        "{%0,%1,%2,%3}, {%4,%5,%6,%7}, {%8,%9}, {%0,%1,%2,%3};"
        : "+f"(d[0]), "+f"(d[1]), "+f"(d[2]), "+f"(d[3])
        : "r"(a[0]), "r"(a[1]), "r"(a[2]), "r"(a[3]),
          "r"(b[0]), "r"(b[1]));
}

__device__ __forceinline__ void mma_f16(float* d, uint32_t a0, uint32_t a1, uint32_t a2, uint32_t a3,
                                        uint32_t b0, uint32_t b1) {
    asm volatile(
        "mma.sync.aligned.m16n8k16.row.col.f32.f16.f16.f32 "
        "{%0,%1,%2,%3}, {%4,%5,%6,%7}, {%8,%9}, {%0,%1,%2,%3};"
        : "+f"(d[0]), "+f"(d[1]), "+f"(d[2]), "+f"(d[3])
        : "r"(a0), "r"(a1), "r"(a2), "r"(a3), "r"(b0), "r"(b1));
}

__device__ __forceinline__ void ldmatrix4(uint32_t* x, uint32_t addr) {
    asm volatile("ldmatrix.sync.aligned.m8n8.x4.shared.b16 {%0,%1,%2,%3}, [%4];"
        : "=r"(x[0]), "=r"(x[1]), "=r"(x[2]), "=r"(x[3]) : "r"(addr));
}

// ---------------------------------------------------------------------------
// LoRA fold (outputs tf32-rounded)
// ---------------------------------------------------------------------------
__global__ void __launch_bounds__(256) build_weff_qkv(
    const float* __restrict__ Wq, const float* __restrict__ Aq, const float* __restrict__ Bq,
    const float* __restrict__ Wk, const float* __restrict__ Ak, const float* __restrict__ Bk,
    const float* __restrict__ Wv, const float* __restrict__ Av, const float* __restrict__ Bv)
{
    int idx = blockIdx.x * 256 + threadIdx.x;
    if (idx >= HID * QKV_N) return;
    int h = idx >> 12;
    int j = idx & 4095;
    const float* W; const float* A; const float* Bm; int jj, n;
    if (j < 2048)       { W = Wq; A = Aq; Bm = Bq; jj = j;        n = 2048; }
    else if (j < 3072)  { W = Wk; A = Ak; Bm = Bk; jj = j - 2048; n = 1024; }
    else                { W = Wv; A = Av; Bm = Bv; jj = j - 3072; n = 1024; }
    float acc = W[(size_t)h * n + jj];
    #pragma unroll
    for (int r = 0; r < RANK; r++)
        acc += A[h * RANK + r] * Bm[r * n + jj];
    g_weff[idx] = f2tf32(acc);
}

__global__ void __launch_bounds__(256) build_woeff(
    const float* __restrict__ Wo, const float* __restrict__ Ao, const float* __restrict__ Bo)
{
    int idx = blockIdx.x * 256 + threadIdx.x;
    if (idx >= HID * HID) return;
    int h = idx >> 11;
    int j = idx & 2047;
    float acc = Wo[(size_t)h * HID + j];
    #pragma unroll
    for (int r = 0; r < RANK; r++)
        acc += Ao[h * RANK + r] * Bo[r * HID + j];
    g_woeff[idx] = f2tf32(acc);
}

__global__ void __launch_bounds__(256) cvt_x_tf32(const float* __restrict__ x)
{
    int idx = blockIdx.x * 256 + threadIdx.x;
    const float4 v = ((const float4*)x)[idx];
    float4 o;
    o.x = f2tf32(v.x); o.y = f2tf32(v.y); o.z = f2tf32(v.z); o.w = f2tf32(v.w);
    ((float4*)g_xt)[idx] = o;
}

// ---------------------------------------------------------------------------
// tf32 tensor-core GEMM (unchanged from R4)
// ---------------------------------------------------------------------------
#define BM  128
#define BN  128
#define BKK 32
#define AST 36
#define BST 136
#define SMEM_A_FLOATS (2*BM*AST)
#define SMEM_B_FLOATS (2*BKK*BST)
#define GEMM_SMEM_BYTES ((SMEM_A_FLOATS + SMEM_B_FLOATS) * 4)

__global__ void __launch_bounds__(256, 2) sgemm_tf32(
    const float* __restrict__ A, const float* __restrict__ B, float* __restrict__ C,
    int M, int N, int K)
{
    extern __shared__ float smem[];
    float* sA = smem;
    float* sB = smem + SMEM_A_FLOATS;
    const uint32_t smem_base = (uint32_t)__cvta_generic_to_shared(smem);

    const int tid  = threadIdx.x;
    const int lane = tid & 31;
    const int wid  = tid >> 5;
    const int wr   = wid >> 2;
    const int wc   = wid & 3;
    const int g    = lane >> 2;
    const int c    = lane & 3;
    const int bm   = blockIdx.y * BM;
    const int bn   = blockIdx.x * BN;

    const int am  = tid >> 1;
    const int ak  = (tid & 1) * 16;
    const int bk  = tid >> 3;
    const int bnn = (tid & 7) * 16;

    const float* Aptr = A + (size_t)(bm + am) * K + ak;
    const float* Bptr = B + (size_t)bk * N + bn + bnn;
    const uint32_t dA0 = smem_base + (uint32_t)((am * AST + ak) * 4);
    const uint32_t dB0 = smem_base + (uint32_t)((SMEM_A_FLOATS + bk * BST + bnn) * 4);

    float acc[4][4][4];
    #pragma unroll
    for (int mt = 0; mt < 4; mt++)
        #pragma unroll
        for (int nt = 0; nt < 4; nt++)
            #pragma unroll
            for (int i = 0; i < 4; i++) acc[mt][nt][i] = 0.0f;

    const int nkt = K / BKK;

    {
        #pragma unroll
        for (int i = 0; i < 4; i++) cp16(dA0 + i * 16, Aptr + i * 4);
        #pragma unroll
        for (int i = 0; i < 4; i++) cp16(dB0 + i * 16, Bptr + i * 4);
        asm volatile("cp.async.commit_group;");
    }

    for (int kt = 0; kt < nkt; kt++) {
        const int buf = kt & 1;
        if (kt + 1 < nkt) {
            const int nb = buf ^ 1;
            const float* pa = Aptr + (kt + 1) * BKK;
            const float* pb = Bptr + (size_t)(kt + 1) * BKK * N;
            const uint32_t da = dA0 + (uint32_t)(nb * BM * AST * 4);
            const uint32_t db = dB0 + (uint32_t)(nb * BKK * BST * 4);
            #pragma unroll
            for (int i = 0; i < 4; i++) cp16(da + i * 16, pa + i * 4);
            #pragma unroll
            for (int i = 0; i < 4; i++) cp16(db + i * 16, pb + i * 4);
            asm volatile("cp.async.commit_group;");
            asm volatile("cp.async.wait_group 1;");
        } else {
            asm volatile("cp.async.wait_group 0;");
        }
        __syncthreads();

        const uint32_t* Au = (const uint32_t*)(sA + buf * BM * AST);
        const uint32_t* Bu = (const uint32_t*)(sB + buf * BKK * BST);

        #pragma unroll
        for (int ks = 0; ks < 4; ks++) {
            const int kk = ks * 8;
            uint32_t af[4][4], bf[4][2];
            #pragma unroll
            for (int mt = 0; mt < 4; mt++) {
                const int r0 = wr * 64 + mt * 16 + g;
                af[mt][0] = Au[r0 * AST + kk + c];
                af[mt][1] = Au[(r0 + 8) * AST + kk + c];
                af[mt][2] = Au[r0 * AST + kk + c + 4];
                af[mt][3] = Au[(r0 + 8) * AST + kk + c + 4];
            }
            #pragma unroll
            for (int nt = 0; nt < 4; nt++) {
                const int n0 = wc * 32 + nt * 8 + g;
                bf[nt][0] = Bu[(kk + c) * BST + n0];
                bf[nt][1] = Bu[(kk + c + 4) * BST + n0];
            }
            #pragma unroll
            for (int mt = 0; mt < 4; mt++)
                #pragma unroll
                for (int nt = 0; nt < 4; nt++)
                    mma_tf32(acc[mt][nt], af[mt], bf[nt]);
        }
        __syncthreads();
    }

    #pragma unroll
    for (int mt = 0; mt < 4; mt++) {
        const int r0 = bm + wr * 64 + mt * 16 + g;
        #pragma unroll
        for (int nt = 0; nt < 4; nt++) {
            const int col = bn + wc * 32 + nt * 8 + 2 * c;
            *(float2*)&C[(size_t)r0 * N + col]       = make_float2(acc[mt][nt][0], acc[mt][nt][1]);
            *(float2*)&C[(size_t)(r0 + 8) * N + col] = make_float2(acc[mt][nt][2], acc[mt][nt][3]);
        }
    }
}

// ---------------------------------------------------------------------------
// Epilogue: RMSNorm + RoPE, emit fp16 q/k (+transposed fp16 v) for flash,
// fp32 k/v caches to d_out.
// ---------------------------------------------------------------------------
__global__ void __launch_bounds__(256) qkv_epilogue(
    const int* __restrict__ positions,
    const float* __restrict__ qn_w, const float* __restrict__ kn_w,
    float* __restrict__ dout, int writeKV)
{
    const int bt = blockIdx.x;
    const int w  = threadIdx.x >> 5;
    const int l  = threadIdx.x & 31;
    const int b  = bt >> 11;       // / TT
    const int t  = bt & (TT - 1);

    const float p = (float)positions[bt];
    const float inv0 = exp2f(-(float)l        * (LOG2_THETA / 64.0f));
    const float inv1 = exp2f(-(float)(l + 32) * (LOG2_THETA / 64.0f));
    float s0, c0, s1, c1;
    sincosf(p * inv0, &s0, &c0);
    sincosf(p * inv1, &s1, &c1);

    const float* row = g_qkv + (size_t)bt * QKV_N;

    for (int seg = w; seg < 32; seg += 8) {
        const float* src = row + seg * HD;
        float x0 = src[l], x1 = src[l + 32], x2 = src[l + 64], x3 = src[l + 96];
        if (seg < 24) {
            float ss = x0 * x0 + x1 * x1 + x2 * x2 + x3 * x3;
            #pragma unroll
            for (int off = 16; off; off >>= 1)
                ss += __shfl_xor_sync(0xffffffffu, ss, off);
            float inv = rsqrtf(ss * (1.0f / 128.0f) + 1e-6f);
            const float* nw = (seg < 16) ? qn_w : kn_w;
            float y0 = nw[l]      * x0 * inv;
            float y1 = nw[l + 32] * x1 * inv;
            float y2 = nw[l + 64] * x2 * inv;
            float y3 = nw[l + 96] * x3 * inv;
            float r0 = y0 * c0 - y2 * s0;
            float r2 = y2 * c0 + y0 * s0;
            float r1 = y1 * c1 - y3 * s1;
            float r3 = y3 * c1 + y1 * s1;
            if (seg < 16) {
                __half* dst = g_qh + (size_t)bt * (NH * HD) + seg * HD;
                dst[l]      = __float2half_rn(r0 * SM_SCALE);
                dst[l + 32] = __float2half_rn(r1 * SM_SCALE);
                dst[l + 64] = __float2half_rn(r2 * SM_SCALE);
                dst[l + 96] = __float2half_rn(r3 * SM_SCALE);
            } else {
                int kh = seg - 16;
                size_t off = (size_t)bt * (NKV * HD) + kh * HD;
                __half* dst = g_kh + off;
                dst[l]      = __float2half_rn(r0);
                dst[l + 32] = __float2half_rn(r1);
                dst[l + 64] = __float2half_rn(r2);
                dst[l + 96] = __float2half_rn(r3);
                if (writeKV) {
                    float* dk = dout + KOFF + off;
                    dk[l] = r0; dk[l + 32] = r1; dk[l + 64] = r2; dk[l + 96] = r3;
                }
            }
        } else {
            int vh = seg - 24;
            // transposed fp16 V: [(b,vh)][d][t]
            __half* vt = g_vt + ((size_t)(b * NKV + vh) * HD) * TT + t;
            vt[(size_t)(l)      * TT] = __float2half_rn(x0);
            vt[(size_t)(l + 32) * TT] = __float2half_rn(x1);
            vt[(size_t)(l + 64) * TT] = __float2half_rn(x2);
            vt[(size_t)(l + 96) * TT] = __float2half_rn(x3);
            if (writeKV) {
                size_t off = (size_t)bt * (NKV * HD) + vh * HD;
                float* dv = dout + VOFF + off;
                dv[l] = x0; dv[l + 32] = x1; dv[l + 64] = x2; dv[l + 96] = x3;
            }
        }
    }
}

// ---------------------------------------------------------------------------
// fp16 tensor-core flash attention, causal, GQA.
// 128x128 tiles, 8 warps; warp tile = 16 rows x 128 cols (whole rows per warp
// -> register-only softmax, in-register P fragment repack for PV).
// K row-major fp16 smem, V d-major (transposed) fp16 smem, both stride 136.
// Double-buffered cp.async.
// ---------------------------------------------------------------------------
#define FH_KSTR 136
#define FH_TILE (128 * FH_KSTR)                 // halves per buffer
#define FLASH_SMEM_BYTES (4 * FH_TILE * 2)      // 139264 B

__global__ void __launch_bounds__(256, 1) flash_fp16()
{
    extern __shared__ char fsm_raw[];
    const uint32_t smem_u32 = (uint32_t)__cvta_generic_to_shared(fsm_raw);

    const int tid  = threadIdx.x;
    const int lane = tid & 31;
    const int w    = tid >> 5;        // warp 0..7
    const int g    = lane >> 2;       // 0..7
    const int c    = lane & 3;        // 0..3
    const int qb   = blockIdx.x;
    const int h    = blockIdx.y;
    const int b    = blockIdx.z;
    const int kvh  = h >> 1;

    // ldmatrix lane addressing (matrix m = lane>>3, row r = lane&7)
    const int lm = lane >> 3;
    const int lr = lane & 7;
    const uint32_t lane_off = (uint32_t)((((lm >> 1) * 8 + lr) * FH_KSTR + (lm & 1) * 8) * 2);

    // tile loaders (cp.async)
    const __half* Kg = g_kh + ((size_t)(b * TT)) * (NKV * HD) + kvh * HD;
    const __half* Vg = g_vt + ((size_t)(b * NKV + kvh) * HD) * TT;

    const int ch = tid;   // base chunk id

    auto issueK = [&](int kb, int buf) {
        const uint32_t dst = smem_u32 + (uint32_t)(buf * FH_TILE * 2);
        #pragma unroll
        for (int it = 0; it < 8; it++) {
            int cc = it * 256 + ch;
            int j  = cc >> 4;
            int cx = (cc & 15) * 8;
            cp16(dst + (uint32_t)((j * FH_KSTR + cx) * 2),
                 Kg + (size_t)(kb * 128 + j) * (NKV * HD) + cx);
        }
        asm volatile("cp.async.commit_group;");
    };
    auto issueV = [&](int kb, int buf) {
        const uint32_t dst = smem_u32 + (uint32_t)((2 + buf) * FH_TILE * 2);
        #pragma unroll
        for (int it = 0; it < 8; it++) {
            int cc = it * 256 + ch;
            int d  = cc >> 4;
            int jx = (cc & 15) * 8;
            cp16(dst + (uint32_t)((d * FH_KSTR + jx) * 2),
                 Vg + (size_t)d * TT + kb * 128 + jx);
        }
        asm volatile("cp.async.commit_group;");
    };

    // prefetch tile 0
    issueK(0, 0);
    issueV(0, 0);

    // Q fragments in registers (overlaps with cp.async latency)
    uint32_t qreg[8][4];
    {
        const __half* Qg = g_qh + ((size_t)(b * TT + qb * 128 + w * 16)) * (NH * HD) + h * HD;
        #pragma unroll
        for (int ks = 0; ks < 8; ks++) {
            qreg[ks][0] = *(const uint32_t*)(Qg + (size_t)g * (NH * HD) + ks * 16 + 2 * c);
            qreg[ks][1] = *(const uint32_t*)(Qg + (size_t)(g + 8) * (NH * HD) + ks * 16 + 2 * c);
            qreg[ks][2] = *(const uint32_t*)(Qg + (size_t)g * (NH * HD) + ks * 16 + 8 + 2 * c);
            qreg[ks][3] = *(const uint32_t*)(Qg + (size_t)(g + 8) * (NH * HD) + ks * 16 + 8 + 2 * c);
        }
    }

    float of[16][4];
    #pragma unroll
    for (int nt = 0; nt < 16; nt++)
        #pragma unroll
        for (int i = 0; i < 4; i++) of[nt][i] = 0.0f;
    float m0 = -1e30f, m1 = -1e30f, l0 = 0.0f, l1 = 0.0f;

    for (int kb = 0; kb <= qb; kb++) {
        const int buf = kb & 1;
        asm volatile("cp.async.wait_group 1;");   // K_kb arrived (V_kb may pend)
        __syncthreads();

        // ---- S = Q @ K^T ----
        float sf[16][4];
        #pragma unroll
        for (int nt = 0; nt < 16; nt++)
            #pragma unroll
            for (int i = 0; i < 4; i++) sf[nt][i] = 0.0f;

        const uint32_t kbase = smem_u32 + (uint32_t)(buf * FH_TILE * 2) + lane_off;
        #pragma unroll
        for (int ks = 0; ks < 8; ks++) {
            #pragma unroll
            for (int ntp = 0; ntp < 8; ntp++) {
                uint32_t x[4];
                ldmatrix4(x, kbase + (uint32_t)((ntp * 16 * FH_KSTR + ks * 16) * 2));
                mma_f16(sf[2 * ntp],     qreg[ks][0], qreg[ks][1], qreg[ks][2], qreg[ks][3], x[0], x[1]);
                mma_f16(sf[2 * ntp + 1], qreg[ks][0], qreg[ks][1], qreg[ks][2], qreg[ks][3], x[2], x[3]);
            }
        }

        // ---- causal mask (diag tile) ----
        if (kb == qb) {
            const int row0 = w * 16 + g;
            const int row1 = row0 + 8;
            #pragma unroll
            for (int nt = 0; nt < 16; nt++) {
                const int col = nt * 8 + 2 * c;
                if (col     > row0) sf[nt][0] = -1e30f;
                if (col + 1 > row0) sf[nt][1] = -1e30f;
                if (col     > row1) sf[nt][2] = -1e30f;
                if (col + 1 > row1) sf[nt][3] = -1e30f;
            }
        }

        // ---- register softmax ----
        float mx0 = m0, mx1 = m1;
        #pragma unroll
        for (int nt = 0; nt < 16; nt++) {
            mx0 = fmaxf(mx0, fmaxf(sf[nt][0], sf[nt][1]));
            mx1 = fmaxf(mx1, fmaxf(sf[nt][2], sf[nt][3]));
        }
        mx0 = fmaxf(mx0, __shfl_xor_sync(0xffffffffu, mx0, 1));
        mx0 = fmaxf(mx0, __shfl_xor_sync(0xffffffffu, mx0, 2));
        mx1 = fmaxf(mx1, __shfl_xor_sync(0xffffffffu, mx1, 1));
        mx1 = fmaxf(mx1, __shfl_xor_sync(0xffffffffu, mx1, 2));
        const float a0s = __expf(m0 - mx0);
        const float a1s = __expf(m1 - mx1);
        m0 = mx0; m1 = mx1;

        uint32_t ph0[16], ph1[16];
        float sum0 = 0.0f, sum1 = 0.0f;
        #pragma unroll
        for (int nt = 0; nt < 16; nt++) {
            float p0 = __expf(sf[nt][0] - m0);
            float p1 = __expf(sf[nt][1] - m0);
            float p2 = __expf(sf[nt][2] - m1);
            float p3 = __expf(sf[nt][3] - m1);
            sum0 += p0 + p1;
            sum1 += p2 + p3;
            __half2 h0 = __floats2half2_rn(p0, p1);
            __half2 h1 = __floats2half2_rn(p2, p3);
            ph0[nt] = *(uint32_t*)&h0;
            ph1[nt] = *(uint32_t*)&h1;
        }
        sum0 += __shfl_xor_sync(0xffffffffu, sum0, 1);
        sum0 += __shfl_xor_sync(0xffffffffu, sum0, 2);
        sum1 += __shfl_xor_sync(0xffffffffu, sum1, 1);
        sum1 += __shfl_xor_sync(0xffffffffu, sum1, 2);
        l0 = l0 * a0s + sum0;
        l1 = l1 * a1s + sum1;
        #pragma unroll
        for (int nt = 0; nt < 16; nt++) {
            of[nt][0] *= a0s; of[nt][1] *= a0s;
            of[nt][2] *= a1s; of[nt][3] *= a1s;
        }

        // prefetch next K, then wait for V_kb
        if (kb < qb) {
            issueK(kb + 1, buf ^ 1);
            asm volatile("cp.async.wait_group 1;");   // completes V_kb
        } else {
            asm volatile("cp.async.wait_group 0;");
        }
        __syncthreads();

        // ---- O += P @ V ----
        const uint32_t vbase = smem_u32 + (uint32_t)((2 + buf) * FH_TILE * 2) + lane_off;
        #pragma unroll
        for (int ks = 0; ks < 8; ks++) {
            const uint32_t a0 = ph0[2 * ks],     a1 = ph1[2 * ks];
            const uint32_t a2 = ph0[2 * ks + 1], a3 = ph1[2 * ks + 1];
            #pragma unroll
            for (int ntp = 0; ntp < 8; ntp++) {
                uint32_t x[4];
                ldmatrix4(x, vbase + (uint32_t)((ntp * 16 * FH_KSTR + ks * 16) * 2));
                mma_f16(of[2 * ntp],     a0, a1, a2, a3, x[0], x[1]);
                mma_f16(of[2 * ntp + 1], a0, a1, a2, a3, x[2], x[3]);
            }
        }

        if (kb < qb) issueV(kb + 1, buf ^ 1);
    }

    // ---- normalize + store (tf32-rounded for the O-projection) ----
    const float li0 = 1.0f / l0;
    const float li1 = 1.0f / l1;
    float* Og = g_attn + (size_t)(b * TT + qb * 128 + w * 16) * (NH * HD) + h * HD;
    #pragma unroll
    for (int nt = 0; nt < 16; nt++) {
        const int col = nt * 8 + 2 * c;
        *(float2*)(Og + (size_t)g * (NH * HD) + col) =
            make_float2(f2tf32(of[nt][0] * li0), f2tf32(of[nt][1] * li0));
        *(float2*)(Og + (size_t)(g + 8) * (NH * HD) + col) =
            make_float2(f2tf32(of[nt][2] * li1), f2tf32(of[nt][3] * li1));
    }
}

// ---------------------------------------------------------------------------
// Host launcher
// ---------------------------------------------------------------------------
extern "C" void kernel_launch(void* const* d_in, const int* in_sizes, int n_in,
                              void* d_out, int out_size)
{
    const float* x  = (const float*)d_in[0];
    const int*   positions = (const int*)d_in[2];
    const float* Wq = (const float*)d_in[3];
    const float* Aq = (const float*)d_in[4];
    const float* Bq = (const float*)d_in[5];
    const float* Wk = (const float*)d_in[6];
    const float* Ak = (const float*)d_in[7];
    const float* Bk = (const float*)d_in[8];
    const float* Wv = (const float*)d_in[9];
    const float* Av = (const float*)d_in[10];
    const float* Bv = (const float*)d_in[11];
    const float* Wo = (const float*)d_in[12];
    const float* Ao = (const float*)d_in[13];
    const float* Bo = (const float*)d_in[14];
    const float* qn = (const float*)d_in[15];
    const float* kn = (const float*)d_in[16];
    float* out = (float*)d_out;

    float *p_weff, *p_woeff, *p_xt, *p_qkv, *p_attn;
    cudaGetSymbolAddress((void**)&p_weff,  g_weff);
    cudaGetSymbolAddress((void**)&p_woeff, g_woeff);
    cudaGetSymbolAddress((void**)&p_xt,    g_xt);
    cudaGetSymbolAddress((void**)&p_qkv,   g_qkv);
    cudaGetSymbolAddress((void**)&p_attn,  g_attn);

    // 1) fold LoRA into tf32-rounded effective weights; round x
    build_weff_qkv<<<(HID * QKV_N + 255) / 256, 256>>>(Wq, Aq, Bq, Wk, Ak, Bk, Wv, Av, Bv);
    build_woeff<<<(HID * HID + 255) / 256, 256>>>(Wo, Ao, Bo);
    cvt_x_tf32<<<(BT * HID / 4 + 255) / 256, 256>>>(x);

    // 2) fused QKV projection (tf32 tensor cores)
    cudaFuncSetAttribute(sgemm_tf32, cudaFuncAttributeMaxDynamicSharedMemorySize, GEMM_SMEM_BYTES);
    sgemm_tf32<<<dim3(QKV_N / BN, BT / BM), 256, GEMM_SMEM_BYTES>>>(p_xt, p_weff, p_qkv, BT, QKV_N, HID);

    // 3) RMSNorm + RoPE + fp16 scatter (+ fp32 caches to d_out)
    int writeKV = (out_size >= VOFF + KV_ELEMS) ? 1 : 0;
    qkv_epilogue<<<BT, 256>>>(positions, qn, kn, out, writeKV);

    // 4) causal flash attention (fp16 tensor cores)
    cudaFuncSetAttribute(flash_fp16, cudaFuncAttributeMaxDynamicSharedMemorySize, FLASH_SMEM_BYTES);
    flash_fp16<<<dim3(TT / 128, NH, BB), 256, FLASH_SMEM_BYTES>>>();

    // 5) output projection (tf32 tensor cores)
    sgemm_tf32<<<dim3(HID / BN, BT / BM), 256, GEMM_SMEM_BYTES>>>(p_attn, p_woeff, out, BT, HID, HID);
}

// round 7
// speedup vs baseline: 5.7164x; 1.6322x over previous
#include <cuda_runtime.h>
#include <cuda_fp16.h>
#include <cuda_bf16.h>
#include <cstdint>
#include <cstddef>

// ---------------------------------------------------------------------------
// Problem constants
// ---------------------------------------------------------------------------
#define BB      2
#define TT      2048
#define HID     2048
#define NH      16
#define NKV     8
#define HD      128
#define RANK    16
#define BT      (BB*TT)              // 4096
#define QKV_N   (NH*HD + 2*NKV*HD)   // 4096
#define Y_ELEMS (BT*HID)             // 8388608
#define KV_ELEMS (BT*NKV*HD)         // 2097152
#define KOFF    Y_ELEMS
#define VOFF    (Y_ELEMS + KV_ELEMS)

#define LOG2_THETA 19.9315685693241741f
#define SM_SCALE   0.0883883476483184405f

// ---------------------------------------------------------------------------
// Device scratch
// ---------------------------------------------------------------------------
__device__ __half g_weffh [HID * QKV_N];     // fp16 fused QKV weights (+LoRA)
__device__ __half g_woeffh[HID * HID];       // fp16 O weights (+LoRA)
__device__ __half g_xh    [BT * HID];        // fp16 x
__device__ float  g_qkv   [BT * QKV_N];      // fp32 GEMM output
__device__ __half g_qh    [BT * NH * HD];    // fp16 q (normed, roped, pre-scaled)
__device__ __half g_kh    [BT * NKV * HD];   // fp16 k (normed, roped), row-major
__device__ __half g_vt    [BB * NKV * HD * TT]; // fp16 v, TRANSPOSED: [(b,kvh)][d][t]
__device__ __half g_attnh [BT * NH * HD];    // fp16 attention output

// ---------------------------------------------------------------------------
// Helpers
// ---------------------------------------------------------------------------
__device__ __forceinline__ void cp16(uint32_t dst, const void* src) {
    asm volatile("cp.async.cg.shared.global [%0], [%1], 16;" :: "r"(dst), "l"(src));
}

__device__ __forceinline__ void mma_f16(float* d, uint32_t a0, uint32_t a1, uint32_t a2, uint32_t a3,
                                        uint32_t b0, uint32_t b1) {
    asm volatile(
        "mma.sync.aligned.m16n8k16.row.col.f32.f16.f16.f32 "
        "{%0,%1,%2,%3}, {%4,%5,%6,%7}, {%8,%9}, {%0,%1,%2,%3};"
        : "+f"(d[0]), "+f"(d[1]), "+f"(d[2]), "+f"(d[3])
        : "r"(a0), "r"(a1), "r"(a2), "r"(a3), "r"(b0), "r"(b1));
}

__device__ __forceinline__ void ldmatrix4(uint32_t* x, uint32_t addr) {
    asm volatile("ldmatrix.sync.aligned.m8n8.x4.shared.b16 {%0,%1,%2,%3}, [%4];"
        : "=r"(x[0]), "=r"(x[1]), "=r"(x[2]), "=r"(x[3]) : "r"(addr));
}

__device__ __forceinline__ void ldmatrix4t(uint32_t* x, uint32_t addr) {
    asm volatile("ldmatrix.sync.aligned.m8n8.x4.trans.shared.b16 {%0,%1,%2,%3}, [%4];"
        : "=r"(x[0]), "=r"(x[1]), "=r"(x[2]), "=r"(x[3]) : "r"(addr));
}

// ---------------------------------------------------------------------------
// LoRA fold (outputs fp16)
// ---------------------------------------------------------------------------
__global__ void __launch_bounds__(256) build_weff_qkv(
    const float* __restrict__ Wq, const float* __restrict__ Aq, const float* __restrict__ Bq,
    const float* __restrict__ Wk, const float* __restrict__ Ak, const float* __restrict__ Bk,
    const float* __restrict__ Wv, const float* __restrict__ Av, const float* __restrict__ Bv)
{
    int idx = blockIdx.x * 256 + threadIdx.x;
    if (idx >= HID * QKV_N) return;
    int h = idx >> 12;
    int j = idx & 4095;
    const float* W; const float* A; const float* Bm; int jj, n;
    if (j < 2048)       { W = Wq; A = Aq; Bm = Bq; jj = j;        n = 2048; }
    else if (j < 3072)  { W = Wk; A = Ak; Bm = Bk; jj = j - 2048; n = 1024; }
    else                { W = Wv; A = Av; Bm = Bv; jj = j - 3072; n = 1024; }
    float acc = W[(size_t)h * n + jj];
    #pragma unroll
    for (int r = 0; r < RANK; r++)
        acc += A[h * RANK + r] * Bm[r * n + jj];
    g_weffh[idx] = __float2half_rn(acc);
}

__global__ void __launch_bounds__(256) build_woeff(
    const float* __restrict__ Wo, const float* __restrict__ Ao, const float* __restrict__ Bo)
{
    int idx = blockIdx.x * 256 + threadIdx.x;
    if (idx >= HID * HID) return;
    int h = idx >> 11;
    int j = idx & 2047;
    float acc = Wo[(size_t)h * HID + j];
    #pragma unroll
    for (int r = 0; r < RANK; r++)
        acc += Ao[h * RANK + r] * Bo[r * HID + j];
    g_woeffh[idx] = __float2half_rn(acc);
}

__global__ void __launch_bounds__(256) cvt_x_f16(const float* __restrict__ x)
{
    int idx = blockIdx.x * 256 + threadIdx.x;   // float4 group
    const float4 v = ((const float4*)x)[idx];
    __half2 h0 = __floats2half2_rn(v.x, v.y);
    __half2 h1 = __floats2half2_rn(v.z, v.w);
    uint2 o = make_uint2(*(uint32_t*)&h0, *(uint32_t*)&h1);
    ((uint2*)g_xh)[idx] = o;
}

// ---------------------------------------------------------------------------
// fp16 tensor-core GEMM, NN row-major: C[M,N](fp32) = A[M,K](f16) @ B[K,N](f16)
// Block 128x128x64, 256 threads (8 warps, warp tile 64x32), cp.async double
// buffer, ldmatrix (A) + ldmatrix.trans (B).
// ---------------------------------------------------------------------------
#define HBK  64
#define HAST 72     // A smem row stride (halves): 144 B -> +16 mod 128 per row
#define HBST 136    // B smem row stride (halves): 272 B -> +16 mod 128 per row
#define HSA  (128 * HAST)            // halves per A buffer (9216)
#define HSB  (HBK * HBST)            // halves per B buffer (8704)
#define HGEMM_SMEM_BYTES ((2 * HSA + 2 * HSB) * 2)   // 71680 B

__global__ void __launch_bounds__(256, 2) hgemm_f16(
    const __half* __restrict__ A, const __half* __restrict__ B, float* __restrict__ C,
    int M, int N, int K)
{
    extern __shared__ __half hsm[];
    const uint32_t smem_base = (uint32_t)__cvta_generic_to_shared(hsm);
    const uint32_t bbase_off = (uint32_t)(2 * HSA * 2);   // byte offset of B region

    const int tid  = threadIdx.x;
    const int lane = tid & 31;
    const int w    = tid >> 5;
    const int wr   = w >> 2;            // 0..1
    const int wc   = w & 3;             // 0..3
    const int lm   = lane >> 3;         // ldmatrix matrix id
    const int lr   = lane & 7;
    const int bm   = blockIdx.y * 128;
    const int bn   = blockIdx.x * 128;

    // loader mapping
    const int arow = tid >> 1;                 // 0..127
    const int acol = (tid & 1) * 32;           // 0 or 32 (4 chunks of 8 from here)
    const int brow = tid >> 2;                 // 0..63
    const int bcol = (tid & 3) * 32;           // 4 chunks of 8

    const __half* Aptr = A + (size_t)(bm + arow) * K + acol;
    const __half* Bptr = B + (size_t)brow * N + bn + bcol;
    const uint32_t dA0 = smem_base + (uint32_t)((arow * HAST + acol) * 2);
    const uint32_t dB0 = smem_base + bbase_off + (uint32_t)((brow * HBST + bcol) * 2);

    float acc[4][4][4];
    #pragma unroll
    for (int mt = 0; mt < 4; mt++)
        #pragma unroll
        for (int nt = 0; nt < 4; nt++)
            #pragma unroll
            for (int i = 0; i < 4; i++) acc[mt][nt][i] = 0.0f;

    const int nkt = K / HBK;

    // prefetch tile 0 -> buf 0
    {
        #pragma unroll
        for (int i = 0; i < 4; i++) cp16(dA0 + i * 16, Aptr + i * 8);
        #pragma unroll
        for (int i = 0; i < 4; i++) cp16(dB0 + i * 16, Bptr + i * 8);
        asm volatile("cp.async.commit_group;");
    }

    // fragment lane addressing
    const int a_r = (lm & 1) * 8 + lr;         // row within 16-row m-tile
    const int a_c = (lm >> 1) * 8;             // col within 16-col k-step
    const int b_r = (lm & 1) * 8 + lr;         // k within 16-k step
    const int b_c = (lm >> 1) * 8;             // n within 16-col pair

    for (int kt = 0; kt < nkt; kt++) {
        const int buf = kt & 1;
        if (kt + 1 < nkt) {
            const int nb = buf ^ 1;
            const __half* pa = Aptr + (kt + 1) * HBK;
            const __half* pb = Bptr + (size_t)(kt + 1) * HBK * N;
            const uint32_t da = dA0 + (uint32_t)(nb * HSA * 2);
            const uint32_t db = dB0 + (uint32_t)(nb * HSB * 2);
            #pragma unroll
            for (int i = 0; i < 4; i++) cp16(da + i * 16, pa + i * 8);
            #pragma unroll
            for (int i = 0; i < 4; i++) cp16(db + i * 16, pb + i * 8);
            asm volatile("cp.async.commit_group;");
            asm volatile("cp.async.wait_group 1;");
        } else {
            asm volatile("cp.async.wait_group 0;");
        }
        __syncthreads();

        const uint32_t abuf = smem_base + (uint32_t)(buf * HSA * 2);
        const uint32_t bbuf = smem_base + bbase_off + (uint32_t)(buf * HSB * 2);

        #pragma unroll
        for (int ks = 0; ks < 4; ks++) {
            const int kk = ks * 16;
            uint32_t af[4][4];
            #pragma unroll
            for (int mt = 0; mt < 4; mt++) {
                const int row = wr * 64 + mt * 16 + a_r;
                ldmatrix4(af[mt], abuf + (uint32_t)((row * HAST + kk + a_c) * 2));
            }
            #pragma unroll
            for (int p = 0; p < 2; p++) {
                uint32_t bx[4];
                const int ncol = wc * 32 + p * 16 + b_c;
                ldmatrix4t(bx, bbuf + (uint32_t)(((kk + b_r) * HBST + ncol) * 2));
                #pragma unroll
                for (int mt = 0; mt < 4; mt++) {
                    mma_f16(acc[mt][2 * p],     af[mt][0], af[mt][1], af[mt][2], af[mt][3], bx[0], bx[1]);
                    mma_f16(acc[mt][2 * p + 1], af[mt][0], af[mt][1], af[mt][2], af[mt][3], bx[2], bx[3]);
                }
            }
        }
        __syncthreads();
    }

    // epilogue (C fragment: rows g,g+8; cols 2c,2c+1 per n-tile)
    const int g = lane >> 2;
    const int c = lane & 3;
    #pragma unroll
    for (int mt = 0; mt < 4; mt++) {
        const int r0 = bm + wr * 64 + mt * 16 + g;
        #pragma unroll
        for (int nt = 0; nt < 4; nt++) {
            const int col = bn + wc * 32 + nt * 8 + 2 * c;
            *(float2*)&C[(size_t)r0 * N + col]       = make_float2(acc[mt][nt][0], acc[mt][nt][1]);
            *(float2*)&C[(size_t)(r0 + 8) * N + col] = make_float2(acc[mt][nt][2], acc[mt][nt][3]);
        }
    }
}

// ---------------------------------------------------------------------------
// Epilogue: RMSNorm + RoPE, emit fp16 q/k (+transposed fp16 v) for flash,
// fp32 k/v caches to d_out.
// ---------------------------------------------------------------------------
__global__ void __launch_bounds__(256) qkv_epilogue(
    const int* __restrict__ positions,
    const float* __restrict__ qn_w, const float* __restrict__ kn_w,
    float* __restrict__ dout, int writeKV)
{
    const int bt = blockIdx.x;
    const int w  = threadIdx.x >> 5;
    const int l  = threadIdx.x & 31;
    const int b  = bt >> 11;       // / TT
    const int t  = bt & (TT - 1);

    const float p = (float)positions[bt];
    const float inv0 = exp2f(-(float)l        * (LOG2_THETA / 64.0f));
    const float inv1 = exp2f(-(float)(l + 32) * (LOG2_THETA / 64.0f));
    float s0, c0, s1, c1;
    sincosf(p * inv0, &s0, &c0);
    sincosf(p * inv1, &s1, &c1);

    const float* row = g_qkv + (size_t)bt * QKV_N;

    for (int seg = w; seg < 32; seg += 8) {
        const float* src = row + seg * HD;
        float x0 = src[l], x1 = src[l + 32], x2 = src[l + 64], x3 = src[l + 96];
        if (seg < 24) {
            float ss = x0 * x0 + x1 * x1 + x2 * x2 + x3 * x3;
            #pragma unroll
            for (int off = 16; off; off >>= 1)
                ss += __shfl_xor_sync(0xffffffffu, ss, off);
            float inv = rsqrtf(ss * (1.0f / 128.0f) + 1e-6f);
            const float* nw = (seg < 16) ? qn_w : kn_w;
            float y0 = nw[l]      * x0 * inv;
            float y1 = nw[l + 32] * x1 * inv;
            float y2 = nw[l + 64] * x2 * inv;
            float y3 = nw[l + 96] * x3 * inv;
            float r0 = y0 * c0 - y2 * s0;
            float r2 = y2 * c0 + y0 * s0;
            float r1 = y1 * c1 - y3 * s1;
            float r3 = y3 * c1 + y1 * s1;
            if (seg < 16) {
                __half* dst = g_qh + (size_t)bt * (NH * HD) + seg * HD;
                dst[l]      = __float2half_rn(r0 * SM_SCALE);
                dst[l + 32] = __float2half_rn(r1 * SM_SCALE);
                dst[l + 64] = __float2half_rn(r2 * SM_SCALE);
                dst[l + 96] = __float2half_rn(r3 * SM_SCALE);
            } else {
                int kh = seg - 16;
                size_t off = (size_t)bt * (NKV * HD) + kh * HD;
                __half* dst = g_kh + off;
                dst[l]      = __float2half_rn(r0);
                dst[l + 32] = __float2half_rn(r1);
                dst[l + 64] = __float2half_rn(r2);
                dst[l + 96] = __float2half_rn(r3);
                if (writeKV) {
                    float* dk = dout + KOFF + off;
                    dk[l] = r0; dk[l + 32] = r1; dk[l + 64] = r2; dk[l + 96] = r3;
                }
            }
        } else {
            int vh = seg - 24;
            __half* vt = g_vt + ((size_t)(b * NKV + vh) * HD) * TT + t;
            vt[(size_t)(l)      * TT] = __float2half_rn(x0);
            vt[(size_t)(l + 32) * TT] = __float2half_rn(x1);
            vt[(size_t)(l + 64) * TT] = __float2half_rn(x2);
            vt[(size_t)(l + 96) * TT] = __float2half_rn(x3);
            if (writeKV) {
                size_t off = (size_t)bt * (NKV * HD) + vh * HD;
                float* dv = dout + VOFF + off;
                dv[l] = x0; dv[l + 32] = x1; dv[l + 64] = x2; dv[l + 96] = x3;
            }
        }
    }
}

// ---------------------------------------------------------------------------
// fp16 tensor-core flash attention (unchanged from R6 except fp16 output)
// ---------------------------------------------------------------------------
#define FH_KSTR 136
#define FH_TILE (128 * FH_KSTR)
#define FLASH_SMEM_BYTES (4 * FH_TILE * 2)

__global__ void __launch_bounds__(256, 1) flash_fp16()
{
    extern __shared__ char fsm_raw[];
    const uint32_t smem_u32 = (uint32_t)__cvta_generic_to_shared(fsm_raw);

    const int tid  = threadIdx.x;
    const int lane = tid & 31;
    const int w    = tid >> 5;
    const int g    = lane >> 2;
    const int c    = lane & 3;
    const int qb   = blockIdx.x;
    const int h    = blockIdx.y;
    const int b    = blockIdx.z;
    const int kvh  = h >> 1;

    const int lm = lane >> 3;
    const int lr = lane & 7;
    const uint32_t lane_off = (uint32_t)((((lm >> 1) * 8 + lr) * FH_KSTR + (lm & 1) * 8) * 2);

    const __half* Kg = g_kh + ((size_t)(b * TT)) * (NKV * HD) + kvh * HD;
    const __half* Vg = g_vt + ((size_t)(b * NKV + kvh) * HD) * TT;

    const int ch = tid;

    auto issueK = [&](int kb, int buf) {
        const uint32_t dst = smem_u32 + (uint32_t)(buf * FH_TILE * 2);
        #pragma unroll
        for (int it = 0; it < 8; it++) {
            int cc = it * 256 + ch;
            int j  = cc >> 4;
            int cx = (cc & 15) * 8;
            cp16(dst + (uint32_t)((j * FH_KSTR + cx) * 2),
                 Kg + (size_t)(kb * 128 + j) * (NKV * HD) + cx);
        }
        asm volatile("cp.async.commit_group;");
    };
    auto issueV = [&](int kb, int buf) {
        const uint32_t dst = smem_u32 + (uint32_t)((2 + buf) * FH_TILE * 2);
        #pragma unroll
        for (int it = 0; it < 8; it++) {
            int cc = it * 256 + ch;
            int d  = cc >> 4;
            int jx = (cc & 15) * 8;
            cp16(dst + (uint32_t)((d * FH_KSTR + jx) * 2),
                 Vg + (size_t)d * TT + kb * 128 + jx);
        }
        asm volatile("cp.async.commit_group;");
    };

    issueK(0, 0);
    issueV(0, 0);

    uint32_t qreg[8][4];
    {
        const __half* Qg = g_qh + ((size_t)(b * TT + qb * 128 + w * 16)) * (NH * HD) + h * HD;
        #pragma unroll
        for (int ks = 0; ks < 8; ks++) {
            qreg[ks][0] = *(const uint32_t*)(Qg + (size_t)g * (NH * HD) + ks * 16 + 2 * c);
            qreg[ks][1] = *(const uint32_t*)(Qg + (size_t)(g + 8) * (NH * HD) + ks * 16 + 2 * c);
            qreg[ks][2] = *(const uint32_t*)(Qg + (size_t)g * (NH * HD) + ks * 16 + 8 + 2 * c);
            qreg[ks][3] = *(const uint32_t*)(Qg + (size_t)(g + 8) * (NH * HD) + ks * 16 + 8 + 2 * c);
        }
    }

    float of[16][4];
    #pragma unroll
    for (int nt = 0; nt < 16; nt++)
        #pragma unroll
        for (int i = 0; i < 4; i++) of[nt][i] = 0.0f;
    float m0 = -1e30f, m1 = -1e30f, l0 = 0.0f, l1 = 0.0f;

    for (int kb = 0; kb <= qb; kb++) {
        const int buf = kb & 1;
        asm volatile("cp.async.wait_group 1;");
        __syncthreads();

        float sf[16][4];
        #pragma unroll
        for (int nt = 0; nt < 16; nt++)
            #pragma unroll
            for (int i = 0; i < 4; i++) sf[nt][i] = 0.0f;

        const uint32_t kbase = smem_u32 + (uint32_t)(buf * FH_TILE * 2) + lane_off;
        #pragma unroll
        for (int ks = 0; ks < 8; ks++) {
            #pragma unroll
            for (int ntp = 0; ntp < 8; ntp++) {
                uint32_t x[4];
                ldmatrix4(x, kbase + (uint32_t)((ntp * 16 * FH_KSTR + ks * 16) * 2));
                mma_f16(sf[2 * ntp],     qreg[ks][0], qreg[ks][1], qreg[ks][2], qreg[ks][3], x[0], x[1]);
                mma_f16(sf[2 * ntp + 1], qreg[ks][0], qreg[ks][1], qreg[ks][2], qreg[ks][3], x[2], x[3]);
            }
        }

        if (kb == qb) {
            const int row0 = w * 16 + g;
            const int row1 = row0 + 8;
            #pragma unroll
            for (int nt = 0; nt < 16; nt++) {
                const int col = nt * 8 + 2 * c;
                if (col     > row0) sf[nt][0] = -1e30f;
                if (col + 1 > row0) sf[nt][1] = -1e30f;
                if (col     > row1) sf[nt][2] = -1e30f;
                if (col + 1 > row1) sf[nt][3] = -1e30f;
            }
        }

        float mx0 = m0, mx1 = m1;
        #pragma unroll
        for (int nt = 0; nt < 16; nt++) {
            mx0 = fmaxf(mx0, fmaxf(sf[nt][0], sf[nt][1]));
            mx1 = fmaxf(mx1, fmaxf(sf[nt][2], sf[nt][3]));
        }
        mx0 = fmaxf(mx0, __shfl_xor_sync(0xffffffffu, mx0, 1));
        mx0 = fmaxf(mx0, __shfl_xor_sync(0xffffffffu, mx0, 2));
        mx1 = fmaxf(mx1, __shfl_xor_sync(0xffffffffu, mx1, 1));
        mx1 = fmaxf(mx1, __shfl_xor_sync(0xffffffffu, mx1, 2));
        const float a0s = __expf(m0 - mx0);
        const float a1s = __expf(m1 - mx1);
        m0 = mx0; m1 = mx1;

        uint32_t ph0[16], ph1[16];
        float sum0 = 0.0f, sum1 = 0.0f;
        #pragma unroll
        for (int nt = 0; nt < 16; nt++) {
            float p0 = __expf(sf[nt][0] - m0);
            float p1 = __expf(sf[nt][1] - m0);
            float p2 = __expf(sf[nt][2] - m1);
            float p3 = __expf(sf[nt][3] - m1);
            sum0 += p0 + p1;
            sum1 += p2 + p3;
            __half2 h0 = __floats2half2_rn(p0, p1);
            __half2 h1 = __floats2half2_rn(p2, p3);
            ph0[nt] = *(uint32_t*)&h0;
            ph1[nt] = *(uint32_t*)&h1;
        }
        sum0 += __shfl_xor_sync(0xffffffffu, sum0, 1);
        sum0 += __shfl_xor_sync(0xffffffffu, sum0, 2);
        sum1 += __shfl_xor_sync(0xffffffffu, sum1, 1);
        sum1 += __shfl_xor_sync(0xffffffffu, sum1, 2);
        l0 = l0 * a0s + sum0;
        l1 = l1 * a1s + sum1;
        #pragma unroll
        for (int nt = 0; nt < 16; nt++) {
            of[nt][0] *= a0s; of[nt][1] *= a0s;
            of[nt][2] *= a1s; of[nt][3] *= a1s;
        }

        if (kb < qb) {
            issueK(kb + 1, buf ^ 1);
            asm volatile("cp.async.wait_group 1;");
        } else {
            asm volatile("cp.async.wait_group 0;");
        }
        __syncthreads();

        const uint32_t vbase = smem_u32 + (uint32_t)((2 + buf) * FH_TILE * 2) + lane_off;
        #pragma unroll
        for (int ks = 0; ks < 8; ks++) {
            const uint32_t a0 = ph0[2 * ks],     a1 = ph1[2 * ks];
            const uint32_t a2 = ph0[2 * ks + 1], a3 = ph1[2 * ks + 1];
            #pragma unroll
            for (int ntp = 0; ntp < 8; ntp++) {
                uint32_t x[4];
                ldmatrix4(x, vbase + (uint32_t)((ntp * 16 * FH_KSTR + ks * 16) * 2));
                mma_f16(of[2 * ntp],     a0, a1, a2, a3, x[0], x[1]);
                mma_f16(of[2 * ntp + 1], a0, a1, a2, a3, x[2], x[3]);
            }
        }

        if (kb < qb) issueV(kb + 1, buf ^ 1);
    }

    // ---- normalize + store fp16 for the O-projection ----
    const float li0 = 1.0f / l0;
    const float li1 = 1.0f / l1;
    __half* Og = g_attnh + (size_t)(b * TT + qb * 128 + w * 16) * (NH * HD) + h * HD;
    #pragma unroll
    for (int nt = 0; nt < 16; nt++) {
        const int col = nt * 8 + 2 * c;
        __half2 v0 = __floats2half2_rn(of[nt][0] * li0, of[nt][1] * li0);
        __half2 v1 = __floats2half2_rn(of[nt][2] * li1, of[nt][3] * li1);
        *(uint32_t*)(Og + (size_t)g * (NH * HD) + col)       = *(uint32_t*)&v0;
        *(uint32_t*)(Og + (size_t)(g + 8) * (NH * HD) + col) = *(uint32_t*)&v1;
    }
}

// ---------------------------------------------------------------------------
// Host launcher
// ---------------------------------------------------------------------------
extern "C" void kernel_launch(void* const* d_in, const int* in_sizes, int n_in,
                              void* d_out, int out_size)
{
    const float* x  = (const float*)d_in[0];
    const int*   positions = (const int*)d_in[2];
    const float* Wq = (const float*)d_in[3];
    const float* Aq = (const float*)d_in[4];
    const float* Bq = (const float*)d_in[5];
    const float* Wk = (const float*)d_in[6];
    const float* Ak = (const float*)d_in[7];
    const float* Bk = (const float*)d_in[8];
    const float* Wv = (const float*)d_in[9];
    const float* Av = (const float*)d_in[10];
    const float* Bv = (const float*)d_in[11];
    const float* Wo = (const float*)d_in[12];
    const float* Ao = (const float*)d_in[13];
    const float* Bo = (const float*)d_in[14];
    const float* qn = (const float*)d_in[15];
    const float* kn = (const float*)d_in[16];
    float* out = (float*)d_out;

    __half *p_weffh, *p_woeffh, *p_xh, *p_attnh;
    float  *p_qkv;
    cudaGetSymbolAddress((void**)&p_weffh,  g_weffh);
    cudaGetSymbolAddress((void**)&p_woeffh, g_woeffh);
    cudaGetSymbolAddress((void**)&p_xh,     g_xh);
    cudaGetSymbolAddress((void**)&p_qkv,    g_qkv);
    cudaGetSymbolAddress((void**)&p_attnh,  g_attnh);

    // 1) fold LoRA into fp16 effective weights; convert x to fp16
    build_weff_qkv<<<(HID * QKV_N + 255) / 256, 256>>>(Wq, Aq, Bq, Wk, Ak, Bk, Wv, Av, Bv);
    build_woeff<<<(HID * HID + 255) / 256, 256>>>(Wo, Ao, Bo);
    cvt_x_f16<<<(BT * HID / 4 + 255) / 256, 256>>>(x);

    // 2) fused QKV projection (fp16 tensor cores)
    cudaFuncSetAttribute(hgemm_f16, cudaFuncAttributeMaxDynamicSharedMemorySize, HGEMM_SMEM_BYTES);
    hgemm_f16<<<dim3(QKV_N / 128, BT / 128), 256, HGEMM_SMEM_BYTES>>>(p_xh, p_weffh, p_qkv, BT, QKV_N, HID);

    // 3) RMSNorm + RoPE + fp16 scatter (+ fp32 caches to d_out)
    int writeKV = (out_size >= VOFF + KV_ELEMS) ? 1 : 0;
    qkv_epilogue<<<BT, 256>>>(positions, qn, kn, out, writeKV);

    // 4) causal flash attention (fp16 tensor cores)
    cudaFuncSetAttribute(flash_fp16, cudaFuncAttributeMaxDynamicSharedMemorySize, FLASH_SMEM_BYTES);
    flash_fp16<<<dim3(TT / 128, NH, BB), 256, FLASH_SMEM_BYTES>>>();

    // 5) output projection (fp16 tensor cores)
    hgemm_f16<<<dim3(HID / 128, BT / 128), 256, HGEMM_SMEM_BYTES>>>(p_attnh, p_woeffh, out, BT, HID, HID);
}

// round 9
// speedup vs baseline: 5.8052x; 1.0155x over previous
#include <cuda_runtime.h>
#include <cuda_fp16.h>
#include <cuda_bf16.h>
#include <cstdint>
#include <cstddef>

// ---------------------------------------------------------------------------
// Problem constants
// ---------------------------------------------------------------------------
#define BB      2
#define TT      2048
#define HID     2048
#define NH      16
#define NKV     8
#define HD      128
#define RANK    16
#define BT      (BB*TT)              // 4096
#define QKV_N   (NH*HD + 2*NKV*HD)   // 4096
#define Y_ELEMS (BT*HID)             // 8388608
#define KV_ELEMS (BT*NKV*HD)         // 2097152
#define KOFF    Y_ELEMS
#define VOFF    (Y_ELEMS + KV_ELEMS)

#define LOG2_THETA 19.9315685693241741f
#define SM_SCALE   0.0883883476483184405f

// ---------------------------------------------------------------------------
// Device scratch
// ---------------------------------------------------------------------------
__device__ __half g_weffh [HID * QKV_N];     // fp16 fused QKV weights (+LoRA)
__device__ __half g_woeffh[HID * HID];       // fp16 O weights (+LoRA)
__device__ __half g_xh    [BT * HID];        // fp16 x
__device__ float  g_qkv   [BT * QKV_N];      // fp32 GEMM output
__device__ __half g_qh    [BT * NH * HD];    // fp16 q (normed, roped, pre-scaled)
__device__ __half g_kh    [BT * NKV * HD];   // fp16 k (normed, roped), row-major
__device__ __half g_vt    [BB * NKV * HD * TT]; // fp16 v, TRANSPOSED: [(b,kvh)][d][t]
__device__ __half g_attnh [BT * NH * HD];    // fp16 attention output

// ---------------------------------------------------------------------------
// Helpers
// ---------------------------------------------------------------------------
__device__ __forceinline__ void cp16(uint32_t dst, const void* src) {
    asm volatile("cp.async.cg.shared.global [%0], [%1], 16;" :: "r"(dst), "l"(src));
}

__device__ __forceinline__ void mma_f16(float* d, uint32_t a0, uint32_t a1, uint32_t a2, uint32_t a3,
                                        uint32_t b0, uint32_t b1) {
    asm volatile(
        "mma.sync.aligned.m16n8k16.row.col.f32.f16.f16.f32 "
        "{%0,%1,%2,%3}, {%4,%5,%6,%7}, {%8,%9}, {%0,%1,%2,%3};"
        : "+f"(d[0]), "+f"(d[1]), "+f"(d[2]), "+f"(d[3])
        : "r"(a0), "r"(a1), "r"(a2), "r"(a3), "r"(b0), "r"(b1));
}

__device__ __forceinline__ void ldmatrix4(uint32_t* x, uint32_t addr) {
    asm volatile("ldmatrix.sync.aligned.m8n8.x4.shared.b16 {%0,%1,%2,%3}, [%4];"
        : "=r"(x[0]), "=r"(x[1]), "=r"(x[2]), "=r"(x[3]) : "r"(addr));
}

__device__ __forceinline__ void ldmatrix4t(uint32_t* x, uint32_t addr) {
    asm volatile("ldmatrix.sync.aligned.m8n8.x4.trans.shared.b16 {%0,%1,%2,%3}, [%4];"
        : "=r"(x[0]), "=r"(x[1]), "=r"(x[2]), "=r"(x[3]) : "r"(addr));
}

// ---------------------------------------------------------------------------
// LoRA fold (outputs fp16)
// ---------------------------------------------------------------------------
__global__ void __launch_bounds__(256) build_weff_qkv(
    const float* __restrict__ Wq, const float* __restrict__ Aq, const float* __restrict__ Bq,
    const float* __restrict__ Wk, const float* __restrict__ Ak, const float* __restrict__ Bk,
    const float* __restrict__ Wv, const float* __restrict__ Av, const float* __restrict__ Bv)
{
    int idx = blockIdx.x * 256 + threadIdx.x;
    if (idx >= HID * QKV_N) return;
    int h = idx >> 12;
    int j = idx & 4095;
    const float* W; const float* A; const float* Bm; int jj, n;
    if (j < 2048)       { W = Wq; A = Aq; Bm = Bq; jj = j;        n = 2048; }
    else if (j < 3072)  { W = Wk; A = Ak; Bm = Bk; jj = j - 2048; n = 1024; }
    else                { W = Wv; A = Av; Bm = Bv; jj = j - 3072; n = 1024; }
    float acc = W[(size_t)h * n + jj];
    #pragma unroll
    for (int r = 0; r < RANK; r++)
        acc += A[h * RANK + r] * Bm[r * n + jj];
    g_weffh[idx] = __float2half_rn(acc);
}

__global__ void __launch_bounds__(256) build_woeff(
    const float* __restrict__ Wo, const float* __restrict__ Ao, const float* __restrict__ Bo)
{
    int idx = blockIdx.x * 256 + threadIdx.x;
    if (idx >= HID * HID) return;
    int h = idx >> 11;
    int j = idx & 2047;
    float acc = Wo[(size_t)h * HID + j];
    #pragma unroll
    for (int r = 0; r < RANK; r++)
        acc += Ao[h * RANK + r] * Bo[r * HID + j];
    g_woeffh[idx] = __float2half_rn(acc);
}

__global__ void __launch_bounds__(256) cvt_x_f16(const float* __restrict__ x)
{
    int idx = blockIdx.x * 256 + threadIdx.x;   // float4 group
    const float4 v = ((const float4*)x)[idx];
    __half2 h0 = __floats2half2_rn(v.x, v.y);
    __half2 h1 = __floats2half2_rn(v.z, v.w);
    uint2 o = make_uint2(*(uint32_t*)&h0, *(uint32_t*)&h1);
    ((uint2*)g_xh)[idx] = o;
}

// ---------------------------------------------------------------------------
// fp16 tensor-core GEMM, NN row-major: C[M,N](fp32) = A[M,K](f16) @ B[K,N](f16)
// Block 128x128x64, 256 threads (8 warps, warp tile 64x32).
// 3-stage cp.async pipeline, ONE __syncthreads per K-iteration.
// ---------------------------------------------------------------------------
#define HBK     64
#define HAST    72     // A smem row stride (halves)
#define HBST    136    // B smem row stride (halves)
#define HSA     (128 * HAST)           // halves per A stage (9216)
#define HSB     (HBK * HBST)           // halves per B stage (8704)
#define HSTAGES 3
#define HGEMM_SMEM_BYTES (HSTAGES * (HSA + HSB) * 2)   // 107520 B

__global__ void __launch_bounds__(256, 2) hgemm_f16(
    const __half* __restrict__ A, const __half* __restrict__ B, float* __restrict__ C,
    int M, int N, int K)
{
    extern __shared__ __half hsm[];
    const uint32_t smem_base = (uint32_t)__cvta_generic_to_shared(hsm);
    const uint32_t bbase_off = (uint32_t)(HSTAGES * HSA * 2);   // byte offset of B region

    const int tid  = threadIdx.x;
    const int lane = tid & 31;
    const int w    = tid >> 5;
    const int wr   = w >> 2;            // 0..1
    const int wc   = w & 3;             // 0..3
    const int lm   = lane >> 3;
    const int lr   = lane & 7;
    const int bm   = blockIdx.y * 128;
    const int bn   = blockIdx.x * 128;

    // loader mapping
    const int arow = tid >> 1;                 // 0..127
    const int acol = (tid & 1) * 32;           // 0 or 32 (4 chunks of 8)
    const int brow = tid >> 2;                 // 0..63
    const int bcol = (tid & 3) * 32;           // 4 chunks of 8

    const __half* Aptr = A + (size_t)(bm + arow) * K + acol;
    const __half* Bptr = B + (size_t)brow * N + bn + bcol;
    const uint32_t dA0 = smem_base + (uint32_t)((arow * HAST + acol) * 2);
    const uint32_t dB0 = smem_base + bbase_off + (uint32_t)((brow * HBST + bcol) * 2);

    const int nkt = K / HBK;

    auto prefetch = [&](int kt) {
        const int st = kt % HSTAGES;
        const __half* pa = Aptr + kt * HBK;
        const __half* pb = Bptr + (size_t)kt * HBK * N;
        const uint32_t da = dA0 + (uint32_t)(st * HSA * 2);
        const uint32_t db = dB0 + (uint32_t)(st * HSB * 2);
        #pragma unroll
        for (int i = 0; i < 4; i++) cp16(da + i * 16, pa + i * 8);
        #pragma unroll
        for (int i = 0; i < 4; i++) cp16(db + i * 16, pb + i * 8);
        asm volatile("cp.async.commit_group;");
    };

    float acc[4][4][4];
    #pragma unroll
    for (int mt = 0; mt < 4; mt++)
        #pragma unroll
        for (int nt = 0; nt < 4; nt++)
            #pragma unroll
            for (int i = 0; i < 4; i++) acc[mt][nt][i] = 0.0f;

    // prologue: stages 0 and 1 in flight
    prefetch(0);
    prefetch(1);

    // fragment lane addressing
    const int a_r = (lm & 1) * 8 + lr;
    const int a_c = (lm >> 1) * 8;
    const int b_r = (lm & 1) * 8 + lr;
    const int b_c = (lm >> 1) * 8;

    for (int kt = 0; kt < nkt; kt++) {
        if (kt + 2 <= nkt)
            asm volatile("cp.async.wait_group 1;");
        else
            asm volatile("cp.async.wait_group 0;");
        __syncthreads();

        if (kt + 2 < nkt) prefetch(kt + 2);

        const int st = kt % HSTAGES;
        const uint32_t abuf = smem_base + (uint32_t)(st * HSA * 2);
        const uint32_t bbuf = smem_base + bbase_off + (uint32_t)(st * HSB * 2);

        #pragma unroll
        for (int ks = 0; ks < 4; ks++) {
            const int kk = ks * 16;
            uint32_t af[4][4];
            #pragma unroll
            for (int mt = 0; mt < 4; mt++) {
                const int row = wr * 64 + mt * 16 + a_r;
                ldmatrix4(af[mt], abuf + (uint32_t)((row * HAST + kk + a_c) * 2));
            }
            #pragma unroll
            for (int p = 0; p < 2; p++) {
                uint32_t bx[4];
                const int ncol = wc * 32 + p * 16 + b_c;
                ldmatrix4t(bx, bbuf + (uint32_t)(((kk + b_r) * HBST + ncol) * 2));
                #pragma unroll
                for (int mt = 0; mt < 4; mt++) {
                    mma_f16(acc[mt][2 * p],     af[mt][0], af[mt][1], af[mt][2], af[mt][3], bx[0], bx[1]);
                    mma_f16(acc[mt][2 * p + 1], af[mt][0], af[mt][1], af[mt][2], af[mt][3], bx[2], bx[3]);
                }
            }
        }
    }

    // epilogue
    const int g = lane >> 2;
    const int c = lane & 3;
    #pragma unroll
    for (int mt = 0; mt < 4; mt++) {
        const int r0 = bm + wr * 64 + mt * 16 + g;
        #pragma unroll
        for (int nt = 0; nt < 4; nt++) {
            const int col = bn + wc * 32 + nt * 8 + 2 * c;
            *(float2*)&C[(size_t)r0 * N + col]       = make_float2(acc[mt][nt][0], acc[mt][nt][1]);
            *(float2*)&C[(size_t)(r0 + 8) * N + col] = make_float2(acc[mt][nt][2], acc[mt][nt][3]);
        }
    }
}

// ---------------------------------------------------------------------------
// Epilogue: RMSNorm + RoPE, emit fp16 q/k (+transposed fp16 v) for flash,
// fp32 k/v caches to d_out.
// ---------------------------------------------------------------------------
__global__ void __launch_bounds__(256) qkv_epilogue(
    const int* __restrict__ positions,
    const float* __restrict__ qn_w, const float* __restrict__ kn_w,
    float* __restrict__ dout, int writeKV)
{
    const int bt = blockIdx.x;
    const int w  = threadIdx.x >> 5;
    const int l  = threadIdx.x & 31;
    const int b  = bt >> 11;       // / TT
    const int t  = bt & (TT - 1);

    const float p = (float)positions[bt];
    const float inv0 = exp2f(-(float)l        * (LOG2_THETA / 64.0f));
    const float inv1 = exp2f(-(float)(l + 32) * (LOG2_THETA / 64.0f));
    float s0, c0, s1, c1;
    sincosf(p * inv0, &s0, &c0);
    sincosf(p * inv1, &s1, &c1);

    const float* row = g_qkv + (size_t)bt * QKV_N;

    for (int seg = w; seg < 32; seg += 8) {
        const float* src = row + seg * HD;
        float x0 = src[l], x1 = src[l + 32], x2 = src[l + 64], x3 = src[l + 96];
        if (seg < 24) {
            float ss = x0 * x0 + x1 * x1 + x2 * x2 + x3 * x3;
            #pragma unroll
            for (int off = 16; off; off >>= 1)
                ss += __shfl_xor_sync(0xffffffffu, ss, off);
            float inv = rsqrtf(ss * (1.0f / 128.0f) + 1e-6f);
            const float* nw = (seg < 16) ? qn_w : kn_w;
            float y0 = nw[l]      * x0 * inv;
            float y1 = nw[l + 32] * x1 * inv;
            float y2 = nw[l + 64] * x2 * inv;
            float y3 = nw[l + 96] * x3 * inv;
            float r0 = y0 * c0 - y2 * s0;
            float r2 = y2 * c0 + y0 * s0;
            float r1 = y1 * c1 - y3 * s1;
            float r3 = y3 * c1 + y1 * s1;
            if (seg < 16) {
                __half* dst = g_qh + (size_t)bt * (NH * HD) + seg * HD;
                dst[l]      = __float2half_rn(r0 * SM_SCALE);
                dst[l + 32] = __float2half_rn(r1 * SM_SCALE);
                dst[l + 64] = __float2half_rn(r2 * SM_SCALE);
                dst[l + 96] = __float2half_rn(r3 * SM_SCALE);
            } else {
                int kh = seg - 16;
                size_t off = (size_t)bt * (NKV * HD) + kh * HD;
                __half* dst = g_kh + off;
                dst[l]      = __float2half_rn(r0);
                dst[l + 32] = __float2half_rn(r1);
                dst[l + 64] = __float2half_rn(r2);
                dst[l + 96] = __float2half_rn(r3);
                if (writeKV) {
                    float* dk = dout + KOFF + off;
                    dk[l] = r0; dk[l + 32] = r1; dk[l + 64] = r2; dk[l + 96] = r3;
                }
            }
        } else {
            int vh = seg - 24;
            __half* vt = g_vt + ((size_t)(b * NKV + vh) * HD) * TT + t;
            vt[(size_t)(l)      * TT] = __float2half_rn(x0);
            vt[(size_t)(l + 32) * TT] = __float2half_rn(x1);
            vt[(size_t)(l + 64) * TT] = __float2half_rn(x2);
            vt[(size_t)(l + 96) * TT] = __float2half_rn(x3);
            if (writeKV) {
                size_t off = (size_t)bt * (NKV * HD) + vh * HD;
                float* dv = dout + VOFF + off;
                dv[l] = x0; dv[l + 32] = x1; dv[l + 64] = x2; dv[l + 96] = x3;
            }
        }
    }
}

// ---------------------------------------------------------------------------
// fp16 tensor-core flash attention (unchanged from R7)
// ---------------------------------------------------------------------------
#define FH_KSTR 136
#define FH_TILE (128 * FH_KSTR)
#define FLASH_SMEM_BYTES (4 * FH_TILE * 2)

__global__ void __launch_bounds__(256, 1) flash_fp16()
{
    extern __shared__ char fsm_raw[];
    const uint32_t smem_u32 = (uint32_t)__cvta_generic_to_shared(fsm_raw);

    const int tid  = threadIdx.x;
    const int lane = tid & 31;
    const int w    = tid >> 5;
    const int g    = lane >> 2;
    const int c    = lane & 3;
    const int qb   = blockIdx.x;
    const int h    = blockIdx.y;
    const int b    = blockIdx.z;
    const int kvh  = h >> 1;

    const int lm = lane >> 3;
    const int lr = lane & 7;
    const uint32_t lane_off = (uint32_t)((((lm >> 1) * 8 + lr) * FH_KSTR + (lm & 1) * 8) * 2);

    const __half* Kg = g_kh + ((size_t)(b * TT)) * (NKV * HD) + kvh * HD;
    const __half* Vg = g_vt + ((size_t)(b * NKV + kvh) * HD) * TT;

    const int ch = tid;

    auto issueK = [&](int kb, int buf) {
        const uint32_t dst = smem_u32 + (uint32_t)(buf * FH_TILE * 2);
        #pragma unroll
        for (int it = 0; it < 8; it++) {
            int cc = it * 256 + ch;
            int j  = cc >> 4;
            int cx = (cc & 15) * 8;
            cp16(dst + (uint32_t)((j * FH_KSTR + cx) * 2),
                 Kg + (size_t)(kb * 128 + j) * (NKV * HD) + cx);
        }
        asm volatile("cp.async.commit_group;");
    };
    auto issueV = [&](int kb, int buf) {
        const uint32_t dst = smem_u32 + (uint32_t)((2 + buf) * FH_TILE * 2);
        #pragma unroll
        for (int it = 0; it < 8; it++) {
            int cc = it * 256 + ch;
            int d  = cc >> 4;
            int jx = (cc & 15) * 8;
            cp16(dst + (uint32_t)((d * FH_KSTR + jx) * 2),
                 Vg + (size_t)d * TT + kb * 128 + jx);
        }
        asm volatile("cp.async.commit_group;");
    };

    issueK(0, 0);
    issueV(0, 0);

    uint32_t qreg[8][4];
    {
        const __half* Qg = g_qh + ((size_t)(b * TT + qb * 128 + w * 16)) * (NH * HD) + h * HD;
        #pragma unroll
        for (int ks = 0; ks < 8; ks++) {
            qreg[ks][0] = *(const uint32_t*)(Qg + (size_t)g * (NH * HD) + ks * 16 + 2 * c);
            qreg[ks][1] = *(const uint32_t*)(Qg + (size_t)(g + 8) * (NH * HD) + ks * 16 + 2 * c);
            qreg[ks][2] = *(const uint32_t*)(Qg + (size_t)g * (NH * HD) + ks * 16 + 8 + 2 * c);
            qreg[ks][3] = *(const uint32_t*)(Qg + (size_t)(g + 8) * (NH * HD) + ks * 16 + 8 + 2 * c);
        }
    }

    float of[16][4];
    #pragma unroll
    for (int nt = 0; nt < 16; nt++)
        #pragma unroll
        for (int i = 0; i < 4; i++) of[nt][i] = 0.0f;
    float m0 = -1e30f, m1 = -1e30f, l0 = 0.0f, l1 = 0.0f;

    for (int kb = 0; kb <= qb; kb++) {
        const int buf = kb & 1;
        asm volatile("cp.async.wait_group 1;");
        __syncthreads();

        float sf[16][4];
        #pragma unroll
        for (int nt = 0; nt < 16; nt++)
            #pragma unroll
            for (int i = 0; i < 4; i++) sf[nt][i] = 0.0f;

        const uint32_t kbase = smem_u32 + (uint32_t)(buf * FH_TILE * 2) + lane_off;
        #pragma unroll
        for (int ks = 0; ks < 8; ks++) {
            #pragma unroll
            for (int ntp = 0; ntp < 8; ntp++) {
                uint32_t x[4];
                ldmatrix4(x, kbase + (uint32_t)((ntp * 16 * FH_KSTR + ks * 16) * 2));
                mma_f16(sf[2 * ntp],     qreg[ks][0], qreg[ks][1], qreg[ks][2], qreg[ks][3], x[0], x[1]);
                mma_f16(sf[2 * ntp + 1], qreg[ks][0], qreg[ks][1], qreg[ks][2], qreg[ks][3], x[2], x[3]);
            }
        }

        if (kb == qb) {
            const int row0 = w * 16 + g;
            const int row1 = row0 + 8;
            #pragma unroll
            for (int nt = 0; nt < 16; nt++) {
                const int col = nt * 8 + 2 * c;
                if (col     > row0) sf[nt][0] = -1e30f;
                if (col + 1 > row0) sf[nt][1] = -1e30f;
                if (col     > row1) sf[nt][2] = -1e30f;
                if (col + 1 > row1) sf[nt][3] = -1e30f;
            }
        }

        float mx0 = m0, mx1 = m1;
        #pragma unroll
        for (int nt = 0; nt < 16; nt++) {
            mx0 = fmaxf(mx0, fmaxf(sf[nt][0], sf[nt][1]));
            mx1 = fmaxf(mx1, fmaxf(sf[nt][2], sf[nt][3]));
        }
        mx0 = fmaxf(mx0, __shfl_xor_sync(0xffffffffu, mx0, 1));
        mx0 = fmaxf(mx0, __shfl_xor_sync(0xffffffffu, mx0, 2));
        mx1 = fmaxf(mx1, __shfl_xor_sync(0xffffffffu, mx1, 1));
        mx1 = fmaxf(mx1, __shfl_xor_sync(0xffffffffu, mx1, 2));
        const float a0s = __expf(m0 - mx0);
        const float a1s = __expf(m1 - mx1);
        m0 = mx0; m1 = mx1;

        uint32_t ph0[16], ph1[16];
        float sum0 = 0.0f, sum1 = 0.0f;
        #pragma unroll
        for (int nt = 0; nt < 16; nt++) {
            float p0 = __expf(sf[nt][0] - m0);
            float p1 = __expf(sf[nt][1] - m0);
            float p2 = __expf(sf[nt][2] - m1);
            float p3 = __expf(sf[nt][3] - m1);
            sum0 += p0 + p1;
            sum1 += p2 + p3;
            __half2 h0 = __floats2half2_rn(p0, p1);
            __half2 h1 = __floats2half2_rn(p2, p3);
            ph0[nt] = *(uint32_t*)&h0;
            ph1[nt] = *(uint32_t*)&h1;
        }
        sum0 += __shfl_xor_sync(0xffffffffu, sum0, 1);
        sum0 += __shfl_xor_sync(0xffffffffu, sum0, 2);
        sum1 += __shfl_xor_sync(0xffffffffu, sum1, 1);
        sum1 += __shfl_xor_sync(0xffffffffu, sum1, 2);
        l0 = l0 * a0s + sum0;
        l1 = l1 * a1s + sum1;
        #pragma unroll
        for (int nt = 0; nt < 16; nt++) {
            of[nt][0] *= a0s; of[nt][1] *= a0s;
            of[nt][2] *= a1s; of[nt][3] *= a1s;
        }

        if (kb < qb) {
            issueK(kb + 1, buf ^ 1);
            asm volatile("cp.async.wait_group 1;");
        } else {
            asm volatile("cp.async.wait_group 0;");
        }
        __syncthreads();

        const uint32_t vbase = smem_u32 + (uint32_t)((2 + buf) * FH_TILE * 2) + lane_off;
        #pragma unroll
        for (int ks = 0; ks < 8; ks++) {
            const uint32_t a0 = ph0[2 * ks],     a1 = ph1[2 * ks];
            const uint32_t a2 = ph0[2 * ks + 1], a3 = ph1[2 * ks + 1];
            #pragma unroll
            for (int ntp = 0; ntp < 8; ntp++) {
                uint32_t x[4];
                ldmatrix4(x, vbase + (uint32_t)((ntp * 16 * FH_KSTR + ks * 16) * 2));
                mma_f16(of[2 * ntp],     a0, a1, a2, a3, x[0], x[1]);
                mma_f16(of[2 * ntp + 1], a0, a1, a2, a3, x[2], x[3]);
            }
        }

        if (kb < qb) issueV(kb + 1, buf ^ 1);
    }

    // ---- normalize + store fp16 for the O-projection ----
    const float li0 = 1.0f / l0;
    const float li1 = 1.0f / l1;
    __half* Og = g_attnh + (size_t)(b * TT + qb * 128 + w * 16) * (NH * HD) + h * HD;
    #pragma unroll
    for (int nt = 0; nt < 16; nt++) {
        const int col = nt * 8 + 2 * c;
        __half2 v0 = __floats2half2_rn(of[nt][0] * li0, of[nt][1] * li0);
        __half2 v1 = __floats2half2_rn(of[nt][2] * li1, of[nt][3] * li1);
        *(uint32_t*)(Og + (size_t)g * (NH * HD) + col)       = *(uint32_t*)&v0;
        *(uint32_t*)(Og + (size_t)(g + 8) * (NH * HD) + col) = *(uint32_t*)&v1;
    }
}

// ---------------------------------------------------------------------------
// Host launcher
// ---------------------------------------------------------------------------
extern "C" void kernel_launch(void* const* d_in, const int* in_sizes, int n_in,
                              void* d_out, int out_size)
{
    const float* x  = (const float*)d_in[0];
    const int*   positions = (const int*)d_in[2];
    const float* Wq = (const float*)d_in[3];
    const float* Aq = (const float*)d_in[4];
    const float* Bq = (const float*)d_in[5];
    const float* Wk = (const float*)d_in[6];
    const float* Ak = (const float*)d_in[7];
    const float* Bk = (const float*)d_in[8];
    const float* Wv = (const float*)d_in[9];
    const float* Av = (const float*)d_in[10];
    const float* Bv = (const float*)d_in[11];
    const float* Wo = (const float*)d_in[12];
    const float* Ao = (const float*)d_in[13];
    const float* Bo = (const float*)d_in[14];
    const float* qn = (const float*)d_in[15];
    const float* kn = (const float*)d_in[16];
    float* out = (float*)d_out;

    __half *p_weffh, *p_woeffh, *p_xh, *p_attnh;
    float  *p_qkv;
    cudaGetSymbolAddress((void**)&p_weffh,  g_weffh);
    cudaGetSymbolAddress((void**)&p_woeffh, g_woeffh);
    cudaGetSymbolAddress((void**)&p_xh,     g_xh);
    cudaGetSymbolAddress((void**)&p_qkv,    g_qkv);
    cudaGetSymbolAddress((void**)&p_attnh,  g_attnh);

    // 1) fold LoRA into fp16 effective weights; convert x to fp16
    build_weff_qkv<<<(HID * QKV_N + 255) / 256, 256>>>(Wq, Aq, Bq, Wk, Ak, Bk, Wv, Av, Bv);
    build_woeff<<<(HID * HID + 255) / 256, 256>>>(Wo, Ao, Bo);
    cvt_x_f16<<<(BT * HID / 4 + 255) / 256, 256>>>(x);

    // 2) fused QKV projection (fp16 tensor cores, 3-stage pipeline)
    cudaFuncSetAttribute(hgemm_f16, cudaFuncAttributeMaxDynamicSharedMemorySize, HGEMM_SMEM_BYTES);
    hgemm_f16<<<dim3(QKV_N / 128, BT / 128), 256, HGEMM_SMEM_BYTES>>>(p_xh, p_weffh, p_qkv, BT, QKV_N, HID);

    // 3) RMSNorm + RoPE + fp16 scatter (+ fp32 caches to d_out)
    int writeKV = (out_size >= VOFF + KV_ELEMS) ? 1 : 0;
    qkv_epilogue<<<BT, 256>>>(positions, qn, kn, out, writeKV);

    // 4) causal flash attention (fp16 tensor cores)
    cudaFuncSetAttribute(flash_fp16, cudaFuncAttributeMaxDynamicSharedMemorySize, FLASH_SMEM_BYTES);
    flash_fp16<<<dim3(TT / 128, NH, BB), 256, FLASH_SMEM_BYTES>>>();

    // 5) output projection (fp16 tensor cores, 3-stage pipeline)
    hgemm_f16<<<dim3(HID / 128, BT / 128), 256, HGEMM_SMEM_BYTES>>>(p_attnh, p_woeffh, out, BT, HID, HID);
}